// round 6
// baseline (speedup 1.0000x reference)
#include <cuda_runtime.h>
#include <cuda_fp16.h>
#include <math.h>
#include <stdint.h>

#define N_NODES 100000
#define N_EDGES 1600000
#define DIM 128

typedef unsigned long long ull;

// ---------------- device scratch (no allocations allowed) ----------------
__device__ float  g_h[(size_t)N_NODES * DIM];      // layer-1 output fp32
__device__ __half g_xh[(size_t)N_NODES * DIM];     // x in fp16 (gather path)
__device__ __half g_hh[(size_t)N_NODES * DIM];     // h in fp16 (gather path)
__device__ __half g_aggh[(size_t)N_NODES * DIM];   // aggregation result fp16
__device__ int    g_count[N_NODES];
__device__ int    g_off[N_NODES + 1];
__device__ int    g_cursor[N_NODES];
__device__ int    g_ssrc[N_EDGES];

// ---------------- helpers ----------------
__device__ __forceinline__ __half2 u2h2(unsigned u) {
    __half2 h; *reinterpret_cast<unsigned*>(&h) = u; return h;
}
__device__ __forceinline__ unsigned h2u2(__half2 h) {
    return *reinterpret_cast<unsigned*>(&h);
}
__device__ __forceinline__ ull dup2(float x) {
    ull d;
    asm("mov.b64 %0, {%1, %1};" : "=l"(d) : "r"(__float_as_uint(x)));
    return d;
}
__device__ __forceinline__ void ffma2(ull& d, ull a, ull b) {
    asm("fma.rn.f32x2 %0, %1, %2, %3;" : "=l"(d) : "l"(a), "l"(b), "l"(d));
}
__device__ __forceinline__ float lo32(ull v) { return __uint_as_float((unsigned)v); }
__device__ __forceinline__ float hi32(ull v) { return __uint_as_float((unsigned)(v >> 32)); }

// ---------------- fp32 -> fp16 conversion (8 elems / thread) ----------------
__global__ void k_f2h(const float* __restrict__ in, __half* __restrict__ out, int n8) {
    int i = blockIdx.x * blockDim.x + threadIdx.x;
    if (i >= n8) return;
    float4 a = ((const float4*)in)[2 * i];
    float4 b = ((const float4*)in)[2 * i + 1];
    uint4 o;
    o.x = h2u2(__floats2half2_rn(a.x, a.y));
    o.y = h2u2(__floats2half2_rn(a.z, a.w));
    o.z = h2u2(__floats2half2_rn(b.x, b.y));
    o.w = h2u2(__floats2half2_rn(b.z, b.w));
    ((uint4*)out)[i] = o;
}

// ---------------- CSR build ----------------
__global__ void k_hist(const int* __restrict__ dst) {
    int i = blockIdx.x * blockDim.x + threadIdx.x;
    if (i < N_EDGES) atomicAdd(&g_count[dst[i]], 1);
}

__global__ void k_scan() {
    __shared__ int ssum[1024];
    const int t = threadIdx.x;
    const int CH = (N_NODES + 1023) / 1024;   // 98
    int beg = t * CH;
    int end = beg + CH; if (end > N_NODES) end = N_NODES;
    int s = 0;
    for (int i = beg; i < end; i++) s += g_count[i];
    ssum[t] = s;
    __syncthreads();
    for (int d = 1; d < 1024; d <<= 1) {
        int v = (t >= d) ? ssum[t - d] : 0;
        __syncthreads();
        ssum[t] += v;
        __syncthreads();
    }
    int run = (t == 0) ? 0 : ssum[t - 1];
    for (int i = beg; i < end; i++) {
        g_off[i] = run;
        g_cursor[i] = run;
        run += g_count[i];
    }
    if (t == 0) g_off[N_NODES] = N_EDGES;
}

__global__ void k_bin(const int* __restrict__ src, const int* __restrict__ dst) {
    int i = blockIdx.x * blockDim.x + threadIdx.x;
    if (i < N_EDGES) {
        int d = dst[i];
        int p = atomicAdd(&g_cursor[d], 1);
        g_ssrc[p] = src[i];
    }
}

// ---------------- segment max (fp16): one warp per node, MLP-4 ----------------
// Row = 128 halfs = 256B; lane covers 4 halfs (uint2 = 2 half2).
__global__ void k_segmax_h(const __half* __restrict__ feat, __half* __restrict__ agg) {
    int gw = (blockIdx.x * blockDim.x + threadIdx.x) >> 5;
    if (gw >= N_NODES) return;
    const int lane = threadIdx.x & 31;
    const int beg = __ldg(&g_off[gw]);
    const int end = __ldg(&g_off[gw + 1]);
    const unsigned NEGU = 0xFC00FC00u;              // {-inf, -inf} fp16
    __half2 m0 = u2h2(NEGU), m1 = u2h2(NEGU);
    int e = beg;
    for (; e + 4 <= end; e += 4) {
        int s0 = __ldg(&g_ssrc[e]);
        int s1 = __ldg(&g_ssrc[e + 1]);
        int s2 = __ldg(&g_ssrc[e + 2]);
        int s3 = __ldg(&g_ssrc[e + 3]);
        uint2 v0 = __ldg((const uint2*)(feat + (size_t)s0 * DIM) + lane);
        uint2 v1 = __ldg((const uint2*)(feat + (size_t)s1 * DIM) + lane);
        uint2 v2 = __ldg((const uint2*)(feat + (size_t)s2 * DIM) + lane);
        uint2 v3 = __ldg((const uint2*)(feat + (size_t)s3 * DIM) + lane);
        m0 = __hmax2(__hmax2(__hmax2(m0, u2h2(v0.x)), __hmax2(u2h2(v1.x), u2h2(v2.x))), u2h2(v3.x));
        m1 = __hmax2(__hmax2(__hmax2(m1, u2h2(v0.y)), __hmax2(u2h2(v1.y), u2h2(v2.y))), u2h2(v3.y));
    }
    for (; e < end; e++) {
        int s = __ldg(&g_ssrc[e]);
        uint2 v = __ldg((const uint2*)(feat + (size_t)s * DIM) + lane);
        m0 = __hmax2(m0, u2h2(v.x));
        m1 = __hmax2(m1, u2h2(v.y));
    }
    if (beg == end) { m0 = u2h2(0u); m1 = u2h2(0u); }   // PyG: no-edge nodes -> 0
    uint2 o; o.x = h2u2(m0); o.y = h2u2(m1);
    ((uint2*)(agg + (size_t)gw * DIM))[lane] = o;
}

// ---------------- fused GEMM: out = L2norm(agg@Wl + x@Wr + b) [+relu] ----------------
// C[64 x DN] = A[64 x 256] * W[256 x DN], A = [aggh(fp16) | xin(fp32)], W = [Wl ; Wr]
// 256 threads; thread tile 4 rows x TC cols. W column-pairs read from smem as
// packed fp32x2 directly; only 4 A scalars dup'd per k. Register prefetch pipeline.
template <int DN, bool RELU, bool WH>
__global__ void __launch_bounds__(256, 2)
k_gemm(const __half* __restrict__ aggh, const float* __restrict__ xin,
       const float* __restrict__ Wl, const float* __restrict__ Wr,
       const float* __restrict__ bias, float* __restrict__ out,
       __half* __restrict__ outh) {
    constexpr int KC  = 32;
    constexpr int MT  = 64;
    constexpr int AST = 68;              // sA k-row stride (floats); mult of 4 for LDS.128
    constexpr int TC  = DN / 16;         // cols per thread: 8 (DN=128) or 4 (DN=64)
    constexpr int CP  = TC / 2;          // col pairs
    constexpr int WPT = (KC * DN / 4) / 256;  // float4 of W per thread: 4 or 2

    __shared__ float sA[KC * AST];       // [k][m]
    __shared__ float sB[KC * DN];        // [k][n]

    const int tid   = threadIdx.x;
    const int node0 = blockIdx.x * MT;

    // loader mapping: 4 threads per row, 8 consecutive k each
    const int lr = tid >> 2;
    const int lk = (tid & 3) * 8;
    const size_t lrow = (size_t)min(node0 + lr, N_NODES - 1);

    // compute mapping: 16 col-threads x 16 row-threads x 4 rows
    const int tc   = tid & 15;
    const int tr   = tid >> 4;
    const int col0 = tc * TC;
    const int row0 = tr * 4;

    ull acc[4][CP];
#pragma unroll
    for (int r = 0; r < 4; r++)
#pragma unroll
        for (int c = 0; c < CP; c++) acc[r][c] = 0ull;

    uint4  rawA;                 // fp16 A chunk (8 halfs)
    float4 fA0, fA1;             // fp32 A chunk (8 floats)
    float4 fW[WPT];              // W chunk slice

    auto prefetch = [&](int cb) {
        if (cb < 4) {
            rawA = *(const uint4*)(aggh + lrow * DIM + cb * KC + lk);
        } else {
            const float* ap = xin + lrow * DIM + (cb - 4) * KC + lk;
            fA0 = *(const float4*)ap;
            fA1 = *(const float4*)(ap + 4);
        }
        const float4* wp4 = (const float4*)((cb < 4) ? (Wl + (size_t)cb * KC * DN)
                                                     : (Wr + (size_t)(cb - 4) * KC * DN));
#pragma unroll
        for (int j = 0; j < WPT; j++) fW[j] = wp4[tid + j * 256];
    };
    auto stage = [&](int cb) {
        if (cb < 4) {
            unsigned u[4] = {rawA.x, rawA.y, rawA.z, rawA.w};
#pragma unroll
            for (int j = 0; j < 4; j++) {
                __half2 p = u2h2(u[j]);
                sA[(lk + 2 * j)     * AST + lr] = __low2float(p);
                sA[(lk + 2 * j + 1) * AST + lr] = __high2float(p);
            }
        } else {
            float v[8] = {fA0.x, fA0.y, fA0.z, fA0.w, fA1.x, fA1.y, fA1.z, fA1.w};
#pragma unroll
            for (int j = 0; j < 8; j++) sA[(lk + j) * AST + lr] = v[j];
        }
#pragma unroll
        for (int j = 0; j < WPT; j++) ((float4*)sB)[tid + j * 256] = fW[j];
    };

    prefetch(0);
#pragma unroll 1
    for (int cb = 0; cb < 8; cb++) {
        __syncthreads();                 // previous compute done reading smem
        stage(cb);
        __syncthreads();
        if (cb < 7) prefetch(cb + 1);    // LDGs in flight during compute
#pragma unroll
        for (int k = 0; k < KC; k++) {
            float4 a4 = *(const float4*)&sA[k * AST + row0];
            ull ad[4] = {dup2(a4.x), dup2(a4.y), dup2(a4.z), dup2(a4.w)};
            ull wp_[CP];
            {
                ulonglong2 w01 = *(const ulonglong2*)&sB[k * DN + col0];
                wp_[0] = w01.x; wp_[1] = w01.y;
                if (CP == 4) {
                    ulonglong2 w23 = *(const ulonglong2*)&sB[k * DN + col0 + 4];
                    wp_[2] = w23.x; wp_[3] = w23.y;
                }
            }
#pragma unroll
            for (int r = 0; r < 4; r++)
#pragma unroll
                for (int c = 0; c < CP; c++) ffma2(acc[r][c], ad[r], wp_[c]);
        }
    }

    // ---- epilogue: bias, row L2-norm (shfl over 16-lane col group), relu, store
    float bv[TC];
#pragma unroll
    for (int c = 0; c < TC; c++) bv[c] = __ldg(&bias[col0 + c]);

    float ssq[4] = {0.f, 0.f, 0.f, 0.f};
#pragma unroll
    for (int r = 0; r < 4; r++)
#pragma unroll
        for (int c = 0; c < CP; c++) {
            float e = lo32(acc[r][c]) + bv[2 * c];
            float o = hi32(acc[r][c]) + bv[2 * c + 1];
            ssq[r] = fmaf(e, e, fmaf(o, o, ssq[r]));
        }
#pragma unroll
    for (int d = 1; d < 16; d <<= 1)
#pragma unroll
        for (int r = 0; r < 4; r++)
            ssq[r] += __shfl_xor_sync(0xffffffffu, ssq[r], d);

#pragma unroll
    for (int r = 0; r < 4; r++) {
        int node = node0 + row0 + r;
        if (node >= N_NODES) continue;
        float inv = 1.f / fmaxf(sqrtf(ssq[r]), 1e-12f);
        float v[TC];
#pragma unroll
        for (int c = 0; c < CP; c++) {
            float e = (lo32(acc[r][c]) + bv[2 * c])     * inv;
            float o = (hi32(acc[r][c]) + bv[2 * c + 1]) * inv;
            if (RELU) { e = fmaxf(e, 0.f); o = fmaxf(o, 0.f); }
            v[2 * c] = e; v[2 * c + 1] = o;
        }
        float* op = out + (size_t)node * DN + col0;
        *(float4*)op = make_float4(v[0], v[1], v[2], v[3]);
        if (TC == 8)
            *(float4*)(op + 4) = make_float4(v[4], v[5], v[6], v[7]);
        if (WH) {
            uint4 hv;
            hv.x = h2u2(__floats2half2_rn(v[0], v[1]));
            hv.y = h2u2(__floats2half2_rn(v[2], v[3]));
            hv.z = h2u2(__floats2half2_rn(v[4], v[5]));
            hv.w = h2u2(__floats2half2_rn(v[6], v[7]));
            *(uint4*)(outh + (size_t)node * DN + col0) = hv;
        }
    }
}

// ---------------- host ----------------
extern "C" void kernel_launch(void* const* d_in, const int* in_sizes, int n_in,
                              void* d_out, int out_size) {
    const float* x   = (const float*)d_in[0];
    const int*   ei  = (const int*)d_in[1];
    const float* Wl1 = (const float*)d_in[2];
    const float* Wr1 = (const float*)d_in[3];
    const float* b1  = (const float*)d_in[4];
    const float* Wl2 = (const float*)d_in[5];
    const float* Wr2 = (const float*)d_in[6];
    const float* b2  = (const float*)d_in[7];
    float* out = (float*)d_out;

    const int* src = ei;
    const int* dst = ei + N_EDGES;

    float *h; __half *xh, *hh, *aggh; int* cnt;
    cudaGetSymbolAddress((void**)&h, g_h);
    cudaGetSymbolAddress((void**)&xh, g_xh);
    cudaGetSymbolAddress((void**)&hh, g_hh);
    cudaGetSymbolAddress((void**)&aggh, g_aggh);
    cudaGetSymbolAddress((void**)&cnt, g_count);

    const int n8 = N_NODES * DIM / 8;

    // CSR build (max-aggregation is order-invariant -> deterministic)
    cudaMemsetAsync(cnt, 0, N_NODES * sizeof(int));
    k_f2h<<<(n8 + 255) / 256, 256>>>(x, xh, n8);
    k_hist<<<(N_EDGES + 255) / 256, 256>>>(dst);
    k_scan<<<1, 1024>>>();
    k_bin<<<(N_EDGES + 255) / 256, 256>>>(src, dst);

    const int segmax_blocks = (N_NODES * 32 + 255) / 256;
    const int gemm_blocks   = (N_NODES + 63) / 64;     // 1563

    // layer 1  (epilogue also emits fp16 h for layer-2 gather)
    k_segmax_h<<<segmax_blocks, 256>>>(xh, aggh);
    k_gemm<128, true, true><<<gemm_blocks, 256>>>(aggh, x, Wl1, Wr1, b1, h, hh);

    // layer 2
    k_segmax_h<<<segmax_blocks, 256>>>(hh, aggh);
    k_gemm<64, false, false><<<gemm_blocks, 256>>>(aggh, h, Wl2, Wr2, b2, out, nullptr);
}

// round 7
// speedup vs baseline: 1.3458x; 1.3458x over previous
#include <cuda_runtime.h>
#include <cuda_fp16.h>
#include <math.h>
#include <stdint.h>

#define N_NODES 100000
#define N_EDGES 1600000
#define DIM 128

// ---------------- device scratch (no allocations allowed) ----------------
__device__ __half g_xh [(size_t)N_NODES * DIM];
__device__ __half g_xlo[(size_t)N_NODES * DIM];
__device__ __half g_hh [(size_t)N_NODES * DIM];
__device__ __half g_hlo[(size_t)N_NODES * DIM];
__device__ __half g_aggh[(size_t)N_NODES * DIM];
__device__ __half g_wt[98304];          // transposed fp16 hi/lo weights
__device__ int    g_count[N_NODES];
__device__ int    g_off[N_NODES + 1];
__device__ int    g_cursor[N_NODES];
__device__ int    g_ssrc[N_EDGES];

// g_wt layout (all [n][k], k-stride 128):
//  Wl1h:0  Wl1l:16384  Wr1h:32768  Wr1l:49152  Wl2h:65536  Wl2l:73728  Wr2h:81920  Wr2l:90112

// ---------------- helpers ----------------
__device__ __forceinline__ __half2 u2h2(unsigned u) {
    __half2 h; *reinterpret_cast<unsigned*>(&h) = u; return h;
}
__device__ __forceinline__ unsigned h2u2(__half2 h) {
    return *reinterpret_cast<unsigned*>(&h);
}

// ---------------- prep: split fp32 -> fp16 hi + fp16 lo ----------------
__global__ void k_xsplit(const float* __restrict__ x, __half* __restrict__ xh,
                         __half* __restrict__ xlo, int n4) {
    int i = blockIdx.x * blockDim.x + threadIdx.x;
    if (i >= n4) return;
    float4 v = ((const float4*)x)[i];
    __half2 h0 = __floats2half2_rn(v.x, v.y);
    __half2 h1 = __floats2half2_rn(v.z, v.w);
    float2 f0 = __half22float2(h0);
    float2 f1 = __half22float2(h1);
    __half2 l0 = __floats2half2_rn(v.x - f0.x, v.y - f0.y);
    __half2 l1 = __floats2half2_rn(v.z - f1.x, v.w - f1.y);
    ((__half2*)xh)[2 * i] = h0;  ((__half2*)xh)[2 * i + 1] = h1;
    ((__half2*)xlo)[2 * i] = l0; ((__half2*)xlo)[2 * i + 1] = l1;
}

// W [K=128][N] fp32 -> transposed hi/lo fp16 [n][k] (k-stride 128)
__global__ void k_wprep(const float* __restrict__ W, __half* __restrict__ hi,
                        __half* __restrict__ lo, int N) {
    int i = blockIdx.x * blockDim.x + threadIdx.x;
    if (i >= 128 * N) return;
    int k = i / N, n = i % N;
    float v = W[i];
    __half h = __float2half_rn(v);
    hi[n * 128 + k] = h;
    lo[n * 128 + k] = __float2half_rn(v - __half2float(h));
}

// ---------------- CSR build ----------------
__global__ void k_hist(const int* __restrict__ dst) {
    int i = blockIdx.x * blockDim.x + threadIdx.x;
    if (i < N_EDGES) atomicAdd(&g_count[dst[i]], 1);
}

__global__ void k_scan() {
    __shared__ int ssum[1024];
    const int t = threadIdx.x;
    const int CH = (N_NODES + 1023) / 1024;
    int beg = t * CH;
    int end = beg + CH; if (end > N_NODES) end = N_NODES;
    int s = 0;
    for (int i = beg; i < end; i++) s += g_count[i];
    ssum[t] = s;
    __syncthreads();
    for (int d = 1; d < 1024; d <<= 1) {
        int v = (t >= d) ? ssum[t - d] : 0;
        __syncthreads();
        ssum[t] += v;
        __syncthreads();
    }
    int run = (t == 0) ? 0 : ssum[t - 1];
    for (int i = beg; i < end; i++) {
        g_off[i] = run;
        g_cursor[i] = run;
        run += g_count[i];
    }
    if (t == 0) g_off[N_NODES] = N_EDGES;
}

__global__ void k_bin(const int* __restrict__ src, const int* __restrict__ dst) {
    int i = blockIdx.x * blockDim.x + threadIdx.x;
    if (i < N_EDGES) {
        int d = dst[i];
        int p = atomicAdd(&g_cursor[d], 1);
        g_ssrc[p] = src[i];
    }
}

// ---------------- segment max (fp16): one warp per node, MLP-4 ----------------
__global__ void k_segmax_h(const __half* __restrict__ feat, __half* __restrict__ agg) {
    int gw = (blockIdx.x * blockDim.x + threadIdx.x) >> 5;
    if (gw >= N_NODES) return;
    const int lane = threadIdx.x & 31;
    const int beg = __ldg(&g_off[gw]);
    const int end = __ldg(&g_off[gw + 1]);
    const unsigned NEGU = 0xFC00FC00u;
    __half2 m0 = u2h2(NEGU), m1 = u2h2(NEGU);
    int e = beg;
    for (; e + 4 <= end; e += 4) {
        int s0 = __ldg(&g_ssrc[e]);
        int s1 = __ldg(&g_ssrc[e + 1]);
        int s2 = __ldg(&g_ssrc[e + 2]);
        int s3 = __ldg(&g_ssrc[e + 3]);
        uint2 v0 = __ldg((const uint2*)(feat + (size_t)s0 * DIM) + lane);
        uint2 v1 = __ldg((const uint2*)(feat + (size_t)s1 * DIM) + lane);
        uint2 v2 = __ldg((const uint2*)(feat + (size_t)s2 * DIM) + lane);
        uint2 v3 = __ldg((const uint2*)(feat + (size_t)s3 * DIM) + lane);
        m0 = __hmax2(__hmax2(__hmax2(m0, u2h2(v0.x)), __hmax2(u2h2(v1.x), u2h2(v2.x))), u2h2(v3.x));
        m1 = __hmax2(__hmax2(__hmax2(m1, u2h2(v0.y)), __hmax2(u2h2(v1.y), u2h2(v2.y))), u2h2(v3.y));
    }
    for (; e < end; e++) {
        int s = __ldg(&g_ssrc[e]);
        uint2 v = __ldg((const uint2*)(feat + (size_t)s * DIM) + lane);
        m0 = __hmax2(m0, u2h2(v.x));
        m1 = __hmax2(m1, u2h2(v.y));
    }
    if (beg == end) { m0 = u2h2(0u); m1 = u2h2(0u); }
    uint2 o; o.x = h2u2(m0); o.y = h2u2(m1);
    ((uint2*)(agg + (size_t)gw * DIM))[lane] = o;
}

// ---------------- tensor-core GEMM with split-fp16 compensation ----------------
// C[128 x DN] = sum over 5 segments seg: A_seg[128 x 128](fp16) * W_seg[128 x DN](fp16)
// followed by bias + row L2-norm (+relu) epilogue.
struct GemmSegs { const __half* A[5]; const __half* W[5]; };

template <int DN, bool RELU, bool WH>
__global__ void __launch_bounds__(256, 2)
k_gemm_mma(GemmSegs segs, const float* __restrict__ bias,
           float* __restrict__ out, __half* __restrict__ outh,
           __half* __restrict__ outlo) {
    constexpr int KC  = 32;          // k per chunk
    constexpr int AST = 40;          // smem k-stride in halfs (conflict-free for ldmatrix)
    constexpr int NF  = DN / 8;      // n-fragments (16 or 8)
    constexpr int NG  = DN / 16;     // B ldmatrix groups
    constexpr int WJ  = DN / 64;     // W uint4 loads per thread (2 or 1)
    constexpr int NCH = 20;          // 5 segments x 4 chunks

    __shared__ __half sA[2][128 * AST];
    __shared__ __half sW[2][DN * AST];

    const int tid  = threadIdx.x;
    const int warp = tid >> 5;
    const int lane = tid & 31;
    const int node0 = blockIdx.x * 128;
    const int mbase = warp * 16;

    const unsigned saBase = (unsigned)__cvta_generic_to_shared(&sA[0][0]);
    const unsigned swBase = (unsigned)__cvta_generic_to_shared(&sW[0][0]);
    constexpr unsigned SA_BUF = 128 * AST * 2;   // bytes per A buffer
    constexpr unsigned SW_BUF = DN * AST * 2;

    float acc[NF][4];
#pragma unroll
    for (int f = 0; f < NF; f++)
#pragma unroll
        for (int j = 0; j < 4; j++) acc[f][j] = 0.f;

    uint4 ra[2], rw[WJ];

    auto ldg = [&](int c) {
        const int seg = c >> 2;
        const int kc  = (c & 3) * KC;
        const __half* Ap = segs.A[seg];
        const __half* Wp = segs.W[seg];
#pragma unroll
        for (int j = 0; j < 2; j++) {
            int idx = tid + j * 256;
            int row = idx >> 2, ko = (idx & 3) * 8;
            size_t g = (size_t)min(node0 + row, N_NODES - 1) * DIM + kc + ko;
            ra[j] = *(const uint4*)(Ap + g);
        }
#pragma unroll
        for (int j = 0; j < WJ; j++) {
            int idx = tid + j * 256;
            int n = idx >> 2, ko = (idx & 3) * 8;
            rw[j] = *(const uint4*)(Wp + n * 128 + kc + ko);
        }
    };
    auto sts = [&](int buf) {
#pragma unroll
        for (int j = 0; j < 2; j++) {
            int idx = tid + j * 256;
            int row = idx >> 2, ko = (idx & 3) * 8;
            *(uint4*)&sA[buf][row * AST + ko] = ra[j];
        }
#pragma unroll
        for (int j = 0; j < WJ; j++) {
            int idx = tid + j * 256;
            int n = idx >> 2, ko = (idx & 3) * 8;
            *(uint4*)&sW[buf][n * AST + ko] = rw[j];
        }
    };

    // per-lane ldmatrix address offsets (in elements) — fixed per thread
    const int aRow = mbase + (lane & 15);
    const int aKof = (lane >> 4) << 3;                     // 0 or 8
    const int bNof = (lane & 7) + ((lane >= 16) ? 8 : 0);  // within n-group
    const int bKof = (((lane & 15) >= 8) ? 8 : 0);

    // prologue: stage chunk 0
    ldg(0);
    sts(0);
    __syncthreads();

#pragma unroll 1
    for (int c = 0; c < NCH; c++) {
        const int buf = c & 1;
        if (c + 1 < NCH) ldg(c + 1);

        const unsigned sa = saBase + buf * SA_BUF;
        const unsigned sw = swBase + buf * SW_BUF;
#pragma unroll
        for (int kk = 0; kk < KC; kk += 16) {
            unsigned a0, a1, a2, a3;
            {
                unsigned addr = sa + (unsigned)(aRow * AST + kk + aKof) * 2u;
                asm volatile("ldmatrix.sync.aligned.m8n8.x4.shared.b16 {%0,%1,%2,%3}, [%4];"
                             : "=r"(a0), "=r"(a1), "=r"(a2), "=r"(a3) : "r"(addr));
            }
#pragma unroll
            for (int g = 0; g < NG; g++) {
                unsigned b0, b1, b2, b3;
                unsigned addr = sw + (unsigned)((g * 16 + bNof) * AST + kk + bKof) * 2u;
                asm volatile("ldmatrix.sync.aligned.m8n8.x4.shared.b16 {%0,%1,%2,%3}, [%4];"
                             : "=r"(b0), "=r"(b1), "=r"(b2), "=r"(b3) : "r"(addr));
                asm volatile("mma.sync.aligned.m16n8k16.row.col.f32.f16.f16.f32 "
                             "{%0,%1,%2,%3},{%4,%5,%6,%7},{%8,%9},{%0,%1,%2,%3};"
                             : "+f"(acc[2 * g][0]), "+f"(acc[2 * g][1]),
                               "+f"(acc[2 * g][2]), "+f"(acc[2 * g][3])
                             : "r"(a0), "r"(a1), "r"(a2), "r"(a3), "r"(b0), "r"(b1));
                asm volatile("mma.sync.aligned.m16n8k16.row.col.f32.f16.f16.f32 "
                             "{%0,%1,%2,%3},{%4,%5,%6,%7},{%8,%9},{%0,%1,%2,%3};"
                             : "+f"(acc[2 * g + 1][0]), "+f"(acc[2 * g + 1][1]),
                               "+f"(acc[2 * g + 1][2]), "+f"(acc[2 * g + 1][3])
                             : "r"(a0), "r"(a1), "r"(a2), "r"(a3), "r"(b2), "r"(b3));
            }
        }
        if (c + 1 < NCH) sts(buf ^ 1);
        __syncthreads();
    }

    // ---- epilogue: bias, row L2-norm, (relu), store
    const int q2 = (lane & 3) * 2;
    float ssq0 = 0.f, ssq1 = 0.f;
#pragma unroll
    for (int f = 0; f < NF; f++) {
        float b0 = __ldg(&bias[f * 8 + q2]);
        float b1 = __ldg(&bias[f * 8 + q2 + 1]);
        acc[f][0] += b0; acc[f][1] += b1;
        acc[f][2] += b0; acc[f][3] += b1;
        ssq0 = fmaf(acc[f][0], acc[f][0], fmaf(acc[f][1], acc[f][1], ssq0));
        ssq1 = fmaf(acc[f][2], acc[f][2], fmaf(acc[f][3], acc[f][3], ssq1));
    }
    ssq0 += __shfl_xor_sync(0xffffffffu, ssq0, 1);
    ssq0 += __shfl_xor_sync(0xffffffffu, ssq0, 2);
    ssq1 += __shfl_xor_sync(0xffffffffu, ssq1, 1);
    ssq1 += __shfl_xor_sync(0xffffffffu, ssq1, 2);
    const float inv0 = 1.f / fmaxf(sqrtf(ssq0), 1e-12f);
    const float inv1 = 1.f / fmaxf(sqrtf(ssq1), 1e-12f);

    const int r0 = node0 + mbase + (lane >> 2);
    const int r1 = r0 + 8;
#pragma unroll
    for (int f = 0; f < NF; f++) {
        float v0 = acc[f][0] * inv0, v1 = acc[f][1] * inv0;
        float v2 = acc[f][2] * inv1, v3 = acc[f][3] * inv1;
        if (RELU) {
            v0 = fmaxf(v0, 0.f); v1 = fmaxf(v1, 0.f);
            v2 = fmaxf(v2, 0.f); v3 = fmaxf(v3, 0.f);
        }
        const int n = f * 8 + q2;
        if (WH) {
            if (r0 < N_NODES) {
                __half2 h = __floats2half2_rn(v0, v1);
                float2 hf = __half22float2(h);
                __half2 l = __floats2half2_rn(v0 - hf.x, v1 - hf.y);
                *(__half2*)(outh  + (size_t)r0 * DIM + n) = h;
                *(__half2*)(outlo + (size_t)r0 * DIM + n) = l;
            }
            if (r1 < N_NODES) {
                __half2 h = __floats2half2_rn(v2, v3);
                float2 hf = __half22float2(h);
                __half2 l = __floats2half2_rn(v2 - hf.x, v3 - hf.y);
                *(__half2*)(outh  + (size_t)r1 * DIM + n) = h;
                *(__half2*)(outlo + (size_t)r1 * DIM + n) = l;
            }
        } else {
            if (r0 < N_NODES) *(float2*)(out + (size_t)r0 * DN + n) = make_float2(v0, v1);
            if (r1 < N_NODES) *(float2*)(out + (size_t)r1 * DN + n) = make_float2(v2, v3);
        }
    }
}

// ---------------- host ----------------
extern "C" void kernel_launch(void* const* d_in, const int* in_sizes, int n_in,
                              void* d_out, int out_size) {
    const float* x   = (const float*)d_in[0];
    const int*   ei  = (const int*)d_in[1];
    const float* Wl1 = (const float*)d_in[2];
    const float* Wr1 = (const float*)d_in[3];
    const float* b1  = (const float*)d_in[4];
    const float* Wl2 = (const float*)d_in[5];
    const float* Wr2 = (const float*)d_in[6];
    const float* b2  = (const float*)d_in[7];
    float* out = (float*)d_out;

    const int* src = ei;
    const int* dst = ei + N_EDGES;

    __half *xh, *xlo, *hh, *hlo, *aggh, *wt;
    int* cnt;
    cudaGetSymbolAddress((void**)&xh, g_xh);
    cudaGetSymbolAddress((void**)&xlo, g_xlo);
    cudaGetSymbolAddress((void**)&hh, g_hh);
    cudaGetSymbolAddress((void**)&hlo, g_hlo);
    cudaGetSymbolAddress((void**)&aggh, g_aggh);
    cudaGetSymbolAddress((void**)&wt, g_wt);
    cudaGetSymbolAddress((void**)&cnt, g_count);

    __half* wl1h = wt;          __half* wl1l = wt + 16384;
    __half* wr1h = wt + 32768;  __half* wr1l = wt + 49152;
    __half* wl2h = wt + 65536;  __half* wl2l = wt + 73728;
    __half* wr2h = wt + 81920;  __half* wr2l = wt + 90112;

    // prep
    cudaMemsetAsync(cnt, 0, N_NODES * sizeof(int));
    const int n4 = N_NODES * DIM / 4;
    k_xsplit<<<(n4 + 255) / 256, 256>>>(x, xh, xlo, n4);
    k_wprep<<<64, 256>>>(Wl1, wl1h, wl1l, 128);
    k_wprep<<<64, 256>>>(Wr1, wr1h, wr1l, 128);
    k_wprep<<<32, 256>>>(Wl2, wl2h, wl2l, 64);
    k_wprep<<<32, 256>>>(Wr2, wr2h, wr2l, 64);

    // CSR build (max-aggregation is order-invariant -> deterministic)
    k_hist<<<(N_EDGES + 255) / 256, 256>>>(dst);
    k_scan<<<1, 1024>>>();
    k_bin<<<(N_EDGES + 255) / 256, 256>>>(src, dst);

    const int segmax_blocks = (N_NODES * 32 + 255) / 256;
    const int gemm_blocks   = (N_NODES + 127) / 128;   // 782

    // layer 1: C = agg@Wl1h + agg@Wl1l + xh@Wr1h + xh@Wr1l + xlo@Wr1h
    k_segmax_h<<<segmax_blocks, 256>>>(xh, aggh);
    {
        GemmSegs s;
        s.A[0] = aggh; s.W[0] = wl1h;
        s.A[1] = aggh; s.W[1] = wl1l;
        s.A[2] = xh;   s.W[2] = wr1h;
        s.A[3] = xh;   s.W[3] = wr1l;
        s.A[4] = xlo;  s.W[4] = wr1h;
        k_gemm_mma<128, true, true><<<gemm_blocks, 256>>>(s, b1, nullptr, hh, hlo);
    }

    // layer 2
    k_segmax_h<<<segmax_blocks, 256>>>(hh, aggh);
    {
        GemmSegs s;
        s.A[0] = aggh; s.W[0] = wl2h;
        s.A[1] = aggh; s.W[1] = wl2l;
        s.A[2] = hh;   s.W[2] = wr2h;
        s.A[3] = hh;   s.W[3] = wr2l;
        s.A[4] = hlo;  s.W[4] = wr2h;
        k_gemm_mma<64, false, false><<<gemm_blocks, 256>>>(s, b2, out, nullptr, nullptr);
    }
}

// round 11
// speedup vs baseline: 1.4616x; 1.0860x over previous
#include <cuda_runtime.h>
#include <cuda_fp16.h>
#include <math.h>
#include <stdint.h>

#define N_NODES 100000
#define N_EDGES 1600000
#define DIM 128

// ---------------- device scratch (no allocations allowed) ----------------
__device__ __half g_xh [(size_t)N_NODES * DIM];
__device__ __half g_xlo[(size_t)N_NODES * DIM];
__device__ __half g_hh [(size_t)N_NODES * DIM];
__device__ __half g_hlo[(size_t)N_NODES * DIM];
__device__ __half g_aggh[(size_t)N_NODES * DIM];
__device__ __half g_wt[98304];          // transposed fp16 hi/lo weights [n][k]
__device__ int    g_count[N_NODES];
__device__ int    g_off[N_NODES + 1];
__device__ int    g_cursor[N_NODES];
__device__ int    g_ssrc[N_EDGES];

// g_wt layout (all [n][k], k-stride 128):
//  Wl1h:0  Wl1l:16384  Wr1h:32768  Wr1l:49152  Wl2h:65536  Wl2l:73728  Wr2h:81920  Wr2l:90112

// ---------------- helpers ----------------
__device__ __forceinline__ __half2 u2h2(unsigned u) {
    __half2 h; *reinterpret_cast<unsigned*>(&h) = u; return h;
}
__device__ __forceinline__ unsigned h2u2(__half2 h) {
    return *reinterpret_cast<unsigned*>(&h);
}
__device__ __forceinline__ void cp16(uint32_t saddr, const void* gaddr) {
    asm volatile("cp.async.cg.shared.global [%0], [%1], 16;" :: "r"(saddr), "l"(gaddr));
}
__device__ __forceinline__ void cp_commit() {
    asm volatile("cp.async.commit_group;" ::: "memory");
}
template <int N>
__device__ __forceinline__ void cp_wait() {
    asm volatile("cp.async.wait_group %0;" :: "n"(N) : "memory");
}

// ---------------- prep: split fp32 -> fp16 hi + fp16 lo ----------------
__global__ void k_xsplit(const float* __restrict__ x, __half* __restrict__ xh,
                         __half* __restrict__ xlo, int n4) {
    int i = blockIdx.x * blockDim.x + threadIdx.x;
    if (i >= n4) return;
    float4 v = ((const float4*)x)[i];
    __half2 h0 = __floats2half2_rn(v.x, v.y);
    __half2 h1 = __floats2half2_rn(v.z, v.w);
    float2 f0 = __half22float2(h0);
    float2 f1 = __half22float2(h1);
    __half2 l0 = __floats2half2_rn(v.x - f0.x, v.y - f0.y);
    __half2 l1 = __floats2half2_rn(v.z - f1.x, v.w - f1.y);
    ((__half2*)xh)[2 * i] = h0;  ((__half2*)xh)[2 * i + 1] = h1;
    ((__half2*)xlo)[2 * i] = l0; ((__half2*)xlo)[2 * i + 1] = l1;
}

// all 4 weight matrices -> transposed hi/lo fp16 [n][k] in one launch
__global__ void k_wprep_all(const float* __restrict__ Wl1, const float* __restrict__ Wr1,
                            const float* __restrict__ Wl2, const float* __restrict__ Wr2,
                            __half* __restrict__ wt) {
    int i = blockIdx.x * blockDim.x + threadIdx.x;
    if (i >= 49152) return;
    const float* W; int N, hio, loo, li;
    if (i < 16384)      { W = Wl1; N = 128; hio = 0;     loo = 16384; li = i; }
    else if (i < 32768) { W = Wr1; N = 128; hio = 32768; loo = 49152; li = i - 16384; }
    else if (i < 40960) { W = Wl2; N = 64;  hio = 65536; loo = 73728; li = i - 32768; }
    else                { W = Wr2; N = 64;  hio = 81920; loo = 90112; li = i - 40960; }
    int k = li / N, n = li % N;
    float v = W[li];
    __half h = __float2half_rn(v);
    wt[hio + n * 128 + k] = h;
    wt[loo + n * 128 + k] = __float2half_rn(v - __half2float(h));
}

// ---------------- CSR build ----------------
__global__ void k_hist(const int* __restrict__ dst) {
    int i = blockIdx.x * blockDim.x + threadIdx.x;
    if (i < N_EDGES) atomicAdd(&g_count[dst[i]], 1);
}

__global__ void k_scan() {
    __shared__ int ssum[1024];
    const int t = threadIdx.x;
    const int CH = (N_NODES + 1023) / 1024;
    int beg = t * CH;
    int end = beg + CH; if (end > N_NODES) end = N_NODES;
    int s = 0;
    for (int i = beg; i < end; i++) s += g_count[i];
    ssum[t] = s;
    __syncthreads();
    for (int d = 1; d < 1024; d <<= 1) {
        int v = (t >= d) ? ssum[t - d] : 0;
        __syncthreads();
        ssum[t] += v;
        __syncthreads();
    }
    int run = (t == 0) ? 0 : ssum[t - 1];
    for (int i = beg; i < end; i++) {
        g_off[i] = run;
        g_cursor[i] = run;
        run += g_count[i];
    }
    if (t == 0) g_off[N_NODES] = N_EDGES;
}

__global__ void k_bin(const int* __restrict__ src, const int* __restrict__ dst) {
    int i = blockIdx.x * blockDim.x + threadIdx.x;
    if (i < N_EDGES) {
        int d = dst[i];
        int p = atomicAdd(&g_cursor[d], 1);
        g_ssrc[p] = src[i];
    }
}

// ---------------- segment max (fp16): one warp per node, MLP-4 ----------------
__global__ void k_segmax_h(const __half* __restrict__ feat, __half* __restrict__ agg) {
    int gw = (blockIdx.x * blockDim.x + threadIdx.x) >> 5;
    if (gw >= N_NODES) return;
    const int lane = threadIdx.x & 31;
    const int beg = __ldg(&g_off[gw]);
    const int end = __ldg(&g_off[gw + 1]);
    const unsigned NEGU = 0xFC00FC00u;
    __half2 m0 = u2h2(NEGU), m1 = u2h2(NEGU);
    int e = beg;
    for (; e + 4 <= end; e += 4) {
        int s0 = __ldg(&g_ssrc[e]);
        int s1 = __ldg(&g_ssrc[e + 1]);
        int s2 = __ldg(&g_ssrc[e + 2]);
        int s3 = __ldg(&g_ssrc[e + 3]);
        uint2 v0 = __ldg((const uint2*)(feat + (size_t)s0 * DIM) + lane);
        uint2 v1 = __ldg((const uint2*)(feat + (size_t)s1 * DIM) + lane);
        uint2 v2 = __ldg((const uint2*)(feat + (size_t)s2 * DIM) + lane);
        uint2 v3 = __ldg((const uint2*)(feat + (size_t)s3 * DIM) + lane);
        m0 = __hmax2(__hmax2(__hmax2(m0, u2h2(v0.x)), __hmax2(u2h2(v1.x), u2h2(v2.x))), u2h2(v3.x));
        m1 = __hmax2(__hmax2(__hmax2(m1, u2h2(v0.y)), __hmax2(u2h2(v1.y), u2h2(v2.y))), u2h2(v3.y));
    }
    for (; e < end; e++) {
        int s = __ldg(&g_ssrc[e]);
        uint2 v = __ldg((const uint2*)(feat + (size_t)s * DIM) + lane);
        m0 = __hmax2(m0, u2h2(v.x));
        m1 = __hmax2(m1, u2h2(v.y));
    }
    if (beg == end) { m0 = u2h2(0u); m1 = u2h2(0u); }
    uint2 o; o.x = h2u2(m0); o.y = h2u2(m1);
    ((uint2*)(agg + (size_t)gw * DIM))[lane] = o;
}

// ---------------- HMMA GEMM with cp.async 3-stage pipeline ----------------
// C[128 x DN] = sum over 5 segments: A_seg[128 x 128](fp16) @ W_seg[128 x DN](fp16)
// Warp grid 4(M) x 2(N); warp tile 32 x DN/2. Epilogue: bias + row L2-norm (+relu).
struct GemmSegs { const __half* A[5]; const __half* W[5]; };

template <int DN, bool RELU, bool WH>
__global__ void __launch_bounds__(256, 2)
k_gemm_mma(GemmSegs segs, const float* __restrict__ bias,
           float* __restrict__ out, __half* __restrict__ outh,
           __half* __restrict__ outlo) {
    constexpr int KC   = 32;
    constexpr int AST  = 40;                   // smem k-stride (halfs)
    constexpr int NW   = DN / 2;               // n per warp
    constexpr int NG2  = NW / 16;              // B ldmatrix x4 groups per warp (4 or 2)
    constexpr int NF   = NW / 8;               // n8 frags per warp (8 or 4)
    constexpr int WJ   = DN / 64;              // W cp.async per thread (2 or 1)
    constexpr int NCH  = 20;                   // 5 segments x 4 chunks
    constexpr int STG  = 3;
    constexpr int SA_B = 128 * AST * 2;        // A stage bytes
    constexpr int SW_B = DN * AST * 2;         // W stage bytes

    extern __shared__ unsigned char smem[];
    __half* sA = (__half*)smem;                         // [STG][128*AST]
    __half* sW = (__half*)(smem + STG * SA_B);          // [STG][DN*AST]
    float* sbias = (float*)(smem + STG * (SA_B + SW_B));
    float* sSq   = sbias + DN;

    const int tid  = threadIdx.x;
    const int warp = tid >> 5;
    const int lane = tid & 31;
    const int node0  = blockIdx.x * 128;
    const int mbase  = (warp & 3) * 32;
    const int nbase  = (warp >> 2) * NW;

    if (tid < DN)  sbias[tid] = bias[tid];
    if (tid < 128) sSq[tid] = 0.f;

    const uint32_t saU = (uint32_t)__cvta_generic_to_shared(sA);
    const uint32_t swU = (uint32_t)__cvta_generic_to_shared(sW);

    // cp.async mapping
    const int arow = tid >> 2;                 // A: 2 x 16B per thread (rows 0..127)
    const int ako  = (tid & 3) * 8;
    const size_t agrow = (size_t)min(node0 + arow, N_NODES - 1);

    auto issue = [&](int c) {
        const int seg = c >> 2;
        const int kc  = (c & 3) * KC;
        const int buf = c % STG;
        const __half* Ap = segs.A[seg];
        const __half* Wp = segs.W[seg];
#pragma unroll
        for (int j = 0; j < 2; j++) {
            int row = arow + j * 64;
            cp16(saU + buf * SA_B + (uint32_t)(row * AST + ako) * 2u,
                 Ap + (j ? (size_t)min(node0 + row, N_NODES - 1) : agrow) * DIM + kc + ako);
        }
#pragma unroll
        for (int j = 0; j < WJ; j++) {
            int idx = tid + j * 256;
            int n = idx >> 2, ko = (idx & 3) * 8;
            cp16(swU + buf * SW_B + (uint32_t)(n * AST + ko) * 2u,
                 Wp + n * 128 + kc + ko);
        }
    };

    float acc[2][NF][4];
#pragma unroll
    for (int mf = 0; mf < 2; mf++)
#pragma unroll
        for (int f = 0; f < NF; f++)
#pragma unroll
            for (int j = 0; j < 4; j++) acc[mf][f][j] = 0.f;

    // ldmatrix per-lane offsets
    const int aRow = lane & 15;
    const int aKof = (lane >> 4) << 3;
    const int bNof = (lane & 7) + ((lane >= 16) ? 8 : 0);
    const int bKof = (((lane & 15) >= 8) ? 8 : 0);

    issue(0); cp_commit();
    issue(1); cp_commit();

#pragma unroll 1
    for (int c = 0; c < NCH; c++) {
        cp_wait<1>();
        __syncthreads();
        if (c + 2 < NCH) issue(c + 2);
        cp_commit();                       // empty group ok at tail

        const int buf = c % STG;
        const uint32_t sa = saU + buf * SA_B;
        const uint32_t sw = swU + buf * SW_B;
#pragma unroll
        for (int kk = 0; kk < KC; kk += 16) {
            unsigned a[2][4];
#pragma unroll
            for (int mf = 0; mf < 2; mf++) {
                uint32_t addr = sa + (uint32_t)((mbase + mf * 16 + aRow) * AST + kk + aKof) * 2u;
                asm volatile("ldmatrix.sync.aligned.m8n8.x4.shared.b16 {%0,%1,%2,%3}, [%4];"
                             : "=r"(a[mf][0]), "=r"(a[mf][1]), "=r"(a[mf][2]), "=r"(a[mf][3])
                             : "r"(addr));
            }
#pragma unroll
            for (int g = 0; g < NG2; g++) {
                unsigned b0, b1, b2, b3;
                uint32_t addr = sw + (uint32_t)((nbase + g * 16 + bNof) * AST + kk + bKof) * 2u;
                asm volatile("ldmatrix.sync.aligned.m8n8.x4.shared.b16 {%0,%1,%2,%3}, [%4];"
                             : "=r"(b0), "=r"(b1), "=r"(b2), "=r"(b3) : "r"(addr));
#pragma unroll
                for (int mf = 0; mf < 2; mf++) {
                    asm volatile("mma.sync.aligned.m16n8k16.row.col.f32.f16.f16.f32 "
                                 "{%0,%1,%2,%3},{%4,%5,%6,%7},{%8,%9},{%0,%1,%2,%3};"
                                 : "+f"(acc[mf][2 * g][0]), "+f"(acc[mf][2 * g][1]),
                                   "+f"(acc[mf][2 * g][2]), "+f"(acc[mf][2 * g][3])
                                 : "r"(a[mf][0]), "r"(a[mf][1]), "r"(a[mf][2]), "r"(a[mf][3]),
                                   "r"(b0), "r"(b1));
                    asm volatile("mma.sync.aligned.m16n8k16.row.col.f32.f16.f16.f32 "
                                 "{%0,%1,%2,%3},{%4,%5,%6,%7},{%8,%9},{%0,%1,%2,%3};"
                                 : "+f"(acc[mf][2 * g + 1][0]), "+f"(acc[mf][2 * g + 1][1]),
                                   "+f"(acc[mf][2 * g + 1][2]), "+f"(acc[mf][2 * g + 1][3])
                                 : "r"(a[mf][0]), "r"(a[mf][1]), "r"(a[mf][2]), "r"(a[mf][3]),
                                   "r"(b2), "r"(b3));
                }
            }
        }
        __syncthreads();
    }

    // ---- epilogue: bias, cross-warp row L2-norm via smem, (relu), store
    const int q2 = (lane & 3) * 2;
#pragma unroll
    for (int mf = 0; mf < 2; mf++) {
        float s0 = 0.f, s1 = 0.f;
#pragma unroll
        for (int f = 0; f < NF; f++) {
            float b0 = sbias[nbase + f * 8 + q2];
            float b1 = sbias[nbase + f * 8 + q2 + 1];
            acc[mf][f][0] += b0; acc[mf][f][1] += b1;
            acc[mf][f][2] += b0; acc[mf][f][3] += b1;
            s0 = fmaf(acc[mf][f][0], acc[mf][f][0], fmaf(acc[mf][f][1], acc[mf][f][1], s0));
            s1 = fmaf(acc[mf][f][2], acc[mf][f][2], fmaf(acc[mf][f][3], acc[mf][f][3], s1));
        }
        s0 += __shfl_xor_sync(0xffffffffu, s0, 1);
        s0 += __shfl_xor_sync(0xffffffffu, s0, 2);
        s1 += __shfl_xor_sync(0xffffffffu, s1, 1);
        s1 += __shfl_xor_sync(0xffffffffu, s1, 2);
        if ((lane & 3) == 0) {
            atomicAdd(&sSq[mbase + mf * 16 + (lane >> 2)], s0);
            atomicAdd(&sSq[mbase + mf * 16 + 8 + (lane >> 2)], s1);
        }
    }
    __syncthreads();

#pragma unroll
    for (int mf = 0; mf < 2; mf++) {
#pragma unroll
        for (int half = 0; half < 2; half++) {
            const int lrow = mbase + mf * 16 + half * 8 + (lane >> 2);
            const int node = node0 + lrow;
            if (node >= N_NODES) continue;
            const float inv = 1.f / fmaxf(sqrtf(sSq[lrow]), 1e-12f);
#pragma unroll
            for (int f = 0; f < NF; f++) {
                float v0 = acc[mf][f][2 * half] * inv;
                float v1 = acc[mf][f][2 * half + 1] * inv;
                if (RELU) { v0 = fmaxf(v0, 0.f); v1 = fmaxf(v1, 0.f); }
                const int n = nbase + f * 8 + q2;
                if (WH) {
                    __half2 h = __floats2half2_rn(v0, v1);
                    float2 hf = __half22float2(h);
                    __half2 l = __floats2half2_rn(v0 - hf.x, v1 - hf.y);
                    *(__half2*)(outh  + (size_t)node * DIM + n) = h;
                    *(__half2*)(outlo + (size_t)node * DIM + n) = l;
                } else {
                    *(float2*)(out + (size_t)node * DN + n) = make_float2(v0, v1);
                }
            }
        }
    }
}

// ---------------- host ----------------
extern "C" void kernel_launch(void* const* d_in, const int* in_sizes, int n_in,
                              void* d_out, int out_size) {
    const float* x   = (const float*)d_in[0];
    const int*   ei  = (const int*)d_in[1];
    const float* Wl1 = (const float*)d_in[2];
    const float* Wr1 = (const float*)d_in[3];
    const float* b1  = (const float*)d_in[4];
    const float* Wl2 = (const float*)d_in[5];
    const float* Wr2 = (const float*)d_in[6];
    const float* b2  = (const float*)d_in[7];
    float* out = (float*)d_out;

    const int* src = ei;
    const int* dst = ei + N_EDGES;

    __half *xh, *xlo, *hh, *hlo, *aggh, *wt;
    int* cnt;
    cudaGetSymbolAddress((void**)&xh, g_xh);
    cudaGetSymbolAddress((void**)&xlo, g_xlo);
    cudaGetSymbolAddress((void**)&hh, g_hh);
    cudaGetSymbolAddress((void**)&hlo, g_hlo);
    cudaGetSymbolAddress((void**)&aggh, g_aggh);
    cudaGetSymbolAddress((void**)&wt, g_wt);
    cudaGetSymbolAddress((void**)&cnt, g_count);

    __half* wl1h = wt;          __half* wl1l = wt + 16384;
    __half* wr1h = wt + 32768;  __half* wr1l = wt + 49152;
    __half* wl2h = wt + 65536;  __half* wl2l = wt + 73728;
    __half* wr2h = wt + 81920;  __half* wr2l = wt + 90112;

    const int SMEM1 = 3 * (128 * 40 * 2 + 128 * 40 * 2) + (128 + 128) * 4;  // 62464
    const int SMEM2 = 3 * (128 * 40 * 2 + 64 * 40 * 2) + (64 + 128) * 4;    // 46848
    cudaFuncSetAttribute(k_gemm_mma<128, true, true>,
                         cudaFuncAttributeMaxDynamicSharedMemorySize, SMEM1);
    cudaFuncSetAttribute(k_gemm_mma<64, false, false>,
                         cudaFuncAttributeMaxDynamicSharedMemorySize, SMEM2);

    // prep
    cudaMemsetAsync(cnt, 0, N_NODES * sizeof(int));
    const int n4 = N_NODES * DIM / 4;
    k_xsplit<<<(n4 + 255) / 256, 256>>>(x, xh, xlo, n4);
    k_wprep_all<<<192, 256>>>(Wl1, Wr1, Wl2, Wr2, wt);

    // CSR build (max-aggregation is order-invariant -> deterministic)
    k_hist<<<(N_EDGES + 255) / 256, 256>>>(dst);
    k_scan<<<1, 1024>>>();
    k_bin<<<(N_EDGES + 255) / 256, 256>>>(src, dst);

    const int segmax_blocks = (N_NODES * 32 + 255) / 256;
    const int gemm_blocks   = (N_NODES + 127) / 128;   // 782

    // layer 1: C = agg@Wl1h + agg@Wl1l + xh@Wr1h + xh@Wr1l + xlo@Wr1h
    k_segmax_h<<<segmax_blocks, 256>>>(xh, aggh);
    {
        GemmSegs s;
        s.A[0] = aggh; s.W[0] = wl1h;
        s.A[1] = aggh; s.W[1] = wl1l;
        s.A[2] = xh;   s.W[2] = wr1h;
        s.A[3] = xh;   s.W[3] = wr1l;
        s.A[4] = xlo;  s.W[4] = wr1h;
        k_gemm_mma<128, true, true><<<gemm_blocks, 256, SMEM1>>>(s, b1, nullptr, hh, hlo);
    }

    // layer 2
    k_segmax_h<<<segmax_blocks, 256>>>(hh, aggh);
    {
        GemmSegs s;
        s.A[0] = aggh; s.W[0] = wl2h;
        s.A[1] = aggh; s.W[1] = wl2l;
        s.A[2] = hh;   s.W[2] = wr2h;
        s.A[3] = hh;   s.W[3] = wr2l;
        s.A[4] = hlo;  s.W[4] = wr2h;
        k_gemm_mma<64, false, false><<<gemm_blocks, 256, SMEM2>>>(s, b2, out, nullptr, nullptr);
    }
}

// round 12
// speedup vs baseline: 2.3596x; 1.6144x over previous
#include <cuda_runtime.h>
#include <cuda_fp16.h>
#include <math.h>
#include <stdint.h>

#define N_NODES 100000
#define N_EDGES 1600000
#define DIM 128
#define SCAN_BLOCKS 98    // ceil(100000/1024)

// ---------------- device scratch (no allocations allowed) ----------------
__device__ __half g_xh [(size_t)N_NODES * DIM];
__device__ __half g_xlo[(size_t)N_NODES * DIM];
__device__ __half g_hh [(size_t)N_NODES * DIM];
__device__ __half g_hlo[(size_t)N_NODES * DIM];
__device__ __half g_aggh[(size_t)N_NODES * DIM];
__device__ __half g_wt[98304];          // transposed fp16 hi/lo weights [n][k]
__device__ int    g_count[N_NODES];
__device__ int    g_off[N_NODES + 1];
__device__ int    g_cursor[N_NODES];
__device__ int    g_ssrc[N_EDGES];
__device__ int    g_bsum[SCAN_BLOCKS];
__device__ int    g_bpre[SCAN_BLOCKS];

// g_wt layout (all [n][k], k-stride 128):
//  Wl1h:0  Wl1l:16384  Wr1h:32768  Wr1l:49152  Wl2h:65536  Wl2l:73728  Wr2h:81920  Wr2l:90112

// ---------------- helpers ----------------
__device__ __forceinline__ __half2 u2h2(unsigned u) {
    __half2 h; *reinterpret_cast<unsigned*>(&h) = u; return h;
}
__device__ __forceinline__ unsigned h2u2(__half2 h) {
    return *reinterpret_cast<unsigned*>(&h);
}
__device__ __forceinline__ void cp16(uint32_t saddr, const void* gaddr) {
    asm volatile("cp.async.cg.shared.global [%0], [%1], 16;" :: "r"(saddr), "l"(gaddr));
}
__device__ __forceinline__ void cp_commit() {
    asm volatile("cp.async.commit_group;" ::: "memory");
}
template <int N>
__device__ __forceinline__ void cp_wait() {
    asm volatile("cp.async.wait_group %0;" :: "n"(N) : "memory");
}

// ---------------- prep: split fp32 -> fp16 hi + fp16 lo ----------------
__global__ void k_xsplit(const float* __restrict__ x, __half* __restrict__ xh,
                         __half* __restrict__ xlo, int n4) {
    int i = blockIdx.x * blockDim.x + threadIdx.x;
    if (i >= n4) return;
    float4 v = ((const float4*)x)[i];
    __half2 h0 = __floats2half2_rn(v.x, v.y);
    __half2 h1 = __floats2half2_rn(v.z, v.w);
    float2 f0 = __half22float2(h0);
    float2 f1 = __half22float2(h1);
    __half2 l0 = __floats2half2_rn(v.x - f0.x, v.y - f0.y);
    __half2 l1 = __floats2half2_rn(v.z - f1.x, v.w - f1.y);
    ((__half2*)xh)[2 * i] = h0;  ((__half2*)xh)[2 * i + 1] = h1;
    ((__half2*)xlo)[2 * i] = l0; ((__half2*)xlo)[2 * i + 1] = l1;
}

// all 4 weight matrices -> transposed hi/lo fp16 [n][k] in one launch
__global__ void k_wprep_all(const float* __restrict__ Wl1, const float* __restrict__ Wr1,
                            const float* __restrict__ Wl2, const float* __restrict__ Wr2,
                            __half* __restrict__ wt) {
    int i = blockIdx.x * blockDim.x + threadIdx.x;
    if (i >= 49152) return;
    const float* W; int N, hio, loo, li;
    if (i < 16384)      { W = Wl1; N = 128; hio = 0;     loo = 16384; li = i; }
    else if (i < 32768) { W = Wr1; N = 128; hio = 32768; loo = 49152; li = i - 16384; }
    else if (i < 40960) { W = Wl2; N = 64;  hio = 65536; loo = 73728; li = i - 32768; }
    else                { W = Wr2; N = 64;  hio = 81920; loo = 90112; li = i - 40960; }
    int k = li / N, n = li % N;
    float v = W[li];
    __half h = __float2half_rn(v);
    wt[hio + n * 128 + k] = h;
    wt[loo + n * 128 + k] = __float2half_rn(v - __half2float(h));
}

// ---------------- CSR build ----------------
__global__ void k_hist(const int* __restrict__ dst) {
    int i = blockIdx.x * blockDim.x + threadIdx.x;
    if (i < N_EDGES) atomicAdd(&g_count[dst[i]], 1);
}

// ---- two-level parallel scan: bsum -> scanb -> off ----
__global__ void k_bsum() {
    __shared__ int wsum[32];
    const int t = threadIdx.x;
    const int i = blockIdx.x * 1024 + t;
    int v = (i < N_NODES) ? g_count[i] : 0;
#pragma unroll
    for (int d = 16; d > 0; d >>= 1) v += __shfl_down_sync(0xffffffffu, v, d);
    if ((t & 31) == 0) wsum[t >> 5] = v;
    __syncthreads();
    if (t < 32) {
        int s = wsum[t];
#pragma unroll
        for (int d = 16; d > 0; d >>= 1) s += __shfl_down_sync(0xffffffffu, s, d);
        if (t == 0) g_bsum[blockIdx.x] = s;
    }
}

__global__ void k_scanb() {
    __shared__ int sh[128];
    const int t = threadIdx.x;
    int v = (t < SCAN_BLOCKS) ? g_bsum[t] : 0;
    sh[t] = v;
    __syncthreads();
    for (int d = 1; d < 128; d <<= 1) {
        int u = (t >= d) ? sh[t - d] : 0;
        __syncthreads();
        sh[t] += u;
        __syncthreads();
    }
    if (t < SCAN_BLOCKS) g_bpre[t] = sh[t] - v;   // exclusive prefix
}

__global__ void k_off() {
    __shared__ int sh[1024];
    const int t = threadIdx.x;
    const int i = blockIdx.x * 1024 + t;
    int v = (i < N_NODES) ? g_count[i] : 0;
    sh[t] = v;
    __syncthreads();
    for (int d = 1; d < 1024; d <<= 1) {
        int u = (t >= d) ? sh[t - d] : 0;
        __syncthreads();
        sh[t] += u;
        __syncthreads();
    }
    if (i < N_NODES) {
        int off = g_bpre[blockIdx.x] + sh[t] - v;  // exclusive
        g_off[i] = off;
        g_cursor[i] = off;
        if (i == N_NODES - 1) g_off[N_NODES] = N_EDGES;
    }
}

__global__ void k_bin(const int* __restrict__ src, const int* __restrict__ dst) {
    int i = blockIdx.x * blockDim.x + threadIdx.x;
    if (i < N_EDGES) {
        int d = dst[i];
        int p = atomicAdd(&g_cursor[d], 1);
        g_ssrc[p] = src[i];
    }
}

// ---------------- segment max (fp16): one warp per node, MLP-4 ----------------
__global__ void k_segmax_h(const __half* __restrict__ feat, __half* __restrict__ agg) {
    int gw = (blockIdx.x * blockDim.x + threadIdx.x) >> 5;
    if (gw >= N_NODES) return;
    const int lane = threadIdx.x & 31;
    const int beg = __ldg(&g_off[gw]);
    const int end = __ldg(&g_off[gw + 1]);
    const unsigned NEGU = 0xFC00FC00u;
    __half2 m0 = u2h2(NEGU), m1 = u2h2(NEGU);
    int e = beg;
    for (; e + 4 <= end; e += 4) {
        int s0 = __ldg(&g_ssrc[e]);
        int s1 = __ldg(&g_ssrc[e + 1]);
        int s2 = __ldg(&g_ssrc[e + 2]);
        int s3 = __ldg(&g_ssrc[e + 3]);
        uint2 v0 = __ldg((const uint2*)(feat + (size_t)s0 * DIM) + lane);
        uint2 v1 = __ldg((const uint2*)(feat + (size_t)s1 * DIM) + lane);
        uint2 v2 = __ldg((const uint2*)(feat + (size_t)s2 * DIM) + lane);
        uint2 v3 = __ldg((const uint2*)(feat + (size_t)s3 * DIM) + lane);
        m0 = __hmax2(__hmax2(__hmax2(m0, u2h2(v0.x)), __hmax2(u2h2(v1.x), u2h2(v2.x))), u2h2(v3.x));
        m1 = __hmax2(__hmax2(__hmax2(m1, u2h2(v0.y)), __hmax2(u2h2(v1.y), u2h2(v2.y))), u2h2(v3.y));
    }
    for (; e < end; e++) {
        int s = __ldg(&g_ssrc[e]);
        uint2 v = __ldg((const uint2*)(feat + (size_t)s * DIM) + lane);
        m0 = __hmax2(m0, u2h2(v.x));
        m1 = __hmax2(m1, u2h2(v.y));
    }
    if (beg == end) { m0 = u2h2(0u); m1 = u2h2(0u); }
    uint2 o; o.x = h2u2(m0); o.y = h2u2(m1);
    ((uint2*)(agg + (size_t)gw * DIM))[lane] = o;
}

// ---------------- HMMA GEMM with cp.async 3-stage pipeline ----------------
// C[128 x DN] = sum over 5 segments: A_seg[128 x 128](fp16) @ W_seg[128 x DN](fp16)
// Warp grid 4(M) x 2(N); warp tile 32 x DN/2. Epilogue: bias + row L2-norm (+relu).
struct GemmSegs { const __half* A[5]; const __half* W[5]; };

template <int DN, bool RELU, bool WH>
__global__ void __launch_bounds__(256, 2)
k_gemm_mma(GemmSegs segs, const float* __restrict__ bias,
           float* __restrict__ out, __half* __restrict__ outh,
           __half* __restrict__ outlo) {
    constexpr int KC   = 32;
    constexpr int AST  = 40;                   // smem k-stride (halfs)
    constexpr int NW   = DN / 2;               // n per warp
    constexpr int NG2  = NW / 16;              // B ldmatrix x4 groups per warp (4 or 2)
    constexpr int NF   = NW / 8;               // n8 frags per warp (8 or 4)
    constexpr int WJ   = DN / 64;              // W cp.async per thread (2 or 1)
    constexpr int NCH  = 20;                   // 5 segments x 4 chunks
    constexpr int STG  = 3;
    constexpr int SA_B = 128 * AST * 2;        // A stage bytes
    constexpr int SW_B = DN * AST * 2;         // W stage bytes

    extern __shared__ unsigned char smem[];
    __half* sA = (__half*)smem;                         // [STG][128*AST]
    __half* sW = (__half*)(smem + STG * SA_B);          // [STG][DN*AST]
    float* sbias = (float*)(smem + STG * (SA_B + SW_B));
    float* sSq   = sbias + DN;

    const int tid  = threadIdx.x;
    const int warp = tid >> 5;
    const int lane = tid & 31;
    const int node0  = blockIdx.x * 128;
    const int mbase  = (warp & 3) * 32;
    const int nbase  = (warp >> 2) * NW;

    if (tid < DN)  sbias[tid] = bias[tid];
    if (tid < 128) sSq[tid] = 0.f;

    const uint32_t saU = (uint32_t)__cvta_generic_to_shared(sA);
    const uint32_t swU = (uint32_t)__cvta_generic_to_shared(sW);

    // cp.async mapping
    const int arow = tid >> 2;                 // A: 2 x 16B per thread (rows 0..127)
    const int ako  = (tid & 3) * 8;
    const size_t agrow = (size_t)min(node0 + arow, N_NODES - 1);

    auto issue = [&](int c) {
        const int seg = c >> 2;
        const int kc  = (c & 3) * KC;
        const int buf = c % STG;
        const __half* Ap = segs.A[seg];
        const __half* Wp = segs.W[seg];
#pragma unroll
        for (int j = 0; j < 2; j++) {
            int row = arow + j * 64;
            cp16(saU + buf * SA_B + (uint32_t)(row * AST + ako) * 2u,
                 Ap + (j ? (size_t)min(node0 + row, N_NODES - 1) : agrow) * DIM + kc + ako);
        }
#pragma unroll
        for (int j = 0; j < WJ; j++) {
            int idx = tid + j * 256;
            int n = idx >> 2, ko = (idx & 3) * 8;
            cp16(swU + buf * SW_B + (uint32_t)(n * AST + ko) * 2u,
                 Wp + n * 128 + kc + ko);
        }
    };

    float acc[2][NF][4];
#pragma unroll
    for (int mf = 0; mf < 2; mf++)
#pragma unroll
        for (int f = 0; f < NF; f++)
#pragma unroll
            for (int j = 0; j < 4; j++) acc[mf][f][j] = 0.f;

    // ldmatrix per-lane offsets
    const int aRow = lane & 15;
    const int aKof = (lane >> 4) << 3;
    const int bNof = (lane & 7) + ((lane >= 16) ? 8 : 0);
    const int bKof = (((lane & 15) >= 8) ? 8 : 0);

    issue(0); cp_commit();
    issue(1); cp_commit();

#pragma unroll 1
    for (int c = 0; c < NCH; c++) {
        cp_wait<1>();
        __syncthreads();
        if (c + 2 < NCH) issue(c + 2);
        cp_commit();                       // empty group ok at tail

        const int buf = c % STG;
        const uint32_t sa = saU + buf * SA_B;
        const uint32_t sw = swU + buf * SW_B;
#pragma unroll
        for (int kk = 0; kk < KC; kk += 16) {
            unsigned a[2][4];
#pragma unroll
            for (int mf = 0; mf < 2; mf++) {
                uint32_t addr = sa + (uint32_t)((mbase + mf * 16 + aRow) * AST + kk + aKof) * 2u;
                asm volatile("ldmatrix.sync.aligned.m8n8.x4.shared.b16 {%0,%1,%2,%3}, [%4];"
                             : "=r"(a[mf][0]), "=r"(a[mf][1]), "=r"(a[mf][2]), "=r"(a[mf][3])
                             : "r"(addr));
            }
#pragma unroll
            for (int g = 0; g < NG2; g++) {
                unsigned b0, b1, b2, b3;
                uint32_t addr = sw + (uint32_t)((nbase + g * 16 + bNof) * AST + kk + bKof) * 2u;
                asm volatile("ldmatrix.sync.aligned.m8n8.x4.shared.b16 {%0,%1,%2,%3}, [%4];"
                             : "=r"(b0), "=r"(b1), "=r"(b2), "=r"(b3) : "r"(addr));
#pragma unroll
                for (int mf = 0; mf < 2; mf++) {
                    asm volatile("mma.sync.aligned.m16n8k16.row.col.f32.f16.f16.f32 "
                                 "{%0,%1,%2,%3},{%4,%5,%6,%7},{%8,%9},{%0,%1,%2,%3};"
                                 : "+f"(acc[mf][2 * g][0]), "+f"(acc[mf][2 * g][1]),
                                   "+f"(acc[mf][2 * g][2]), "+f"(acc[mf][2 * g][3])
                                 : "r"(a[mf][0]), "r"(a[mf][1]), "r"(a[mf][2]), "r"(a[mf][3]),
                                   "r"(b0), "r"(b1));
                    asm volatile("mma.sync.aligned.m16n8k16.row.col.f32.f16.f16.f32 "
                                 "{%0,%1,%2,%3},{%4,%5,%6,%7},{%8,%9},{%0,%1,%2,%3};"
                                 : "+f"(acc[mf][2 * g + 1][0]), "+f"(acc[mf][2 * g + 1][1]),
                                   "+f"(acc[mf][2 * g + 1][2]), "+f"(acc[mf][2 * g + 1][3])
                                 : "r"(a[mf][0]), "r"(a[mf][1]), "r"(a[mf][2]), "r"(a[mf][3]),
                                   "r"(b2), "r"(b3));
                }
            }
        }
        __syncthreads();
    }

    // ---- epilogue: bias, cross-warp row L2-norm via smem, (relu), store
    const int q2 = (lane & 3) * 2;
#pragma unroll
    for (int mf = 0; mf < 2; mf++) {
        float s0 = 0.f, s1 = 0.f;
#pragma unroll
        for (int f = 0; f < NF; f++) {
            float b0 = sbias[nbase + f * 8 + q2];
            float b1 = sbias[nbase + f * 8 + q2 + 1];
            acc[mf][f][0] += b0; acc[mf][f][1] += b1;
            acc[mf][f][2] += b0; acc[mf][f][3] += b1;
            s0 = fmaf(acc[mf][f][0], acc[mf][f][0], fmaf(acc[mf][f][1], acc[mf][f][1], s0));
            s1 = fmaf(acc[mf][f][2], acc[mf][f][2], fmaf(acc[mf][f][3], acc[mf][f][3], s1));
        }
        s0 += __shfl_xor_sync(0xffffffffu, s0, 1);
        s0 += __shfl_xor_sync(0xffffffffu, s0, 2);
        s1 += __shfl_xor_sync(0xffffffffu, s1, 1);
        s1 += __shfl_xor_sync(0xffffffffu, s1, 2);
        if ((lane & 3) == 0) {
            atomicAdd(&sSq[mbase + mf * 16 + (lane >> 2)], s0);
            atomicAdd(&sSq[mbase + mf * 16 + 8 + (lane >> 2)], s1);
        }
    }
    __syncthreads();

#pragma unroll
    for (int mf = 0; mf < 2; mf++) {
#pragma unroll
        for (int half = 0; half < 2; half++) {
            const int lrow = mbase + mf * 16 + half * 8 + (lane >> 2);
            const int node = node0 + lrow;
            if (node >= N_NODES) continue;
            const float inv = 1.f / fmaxf(sqrtf(sSq[lrow]), 1e-12f);
#pragma unroll
            for (int f = 0; f < NF; f++) {
                float v0 = acc[mf][f][2 * half] * inv;
                float v1 = acc[mf][f][2 * half + 1] * inv;
                if (RELU) { v0 = fmaxf(v0, 0.f); v1 = fmaxf(v1, 0.f); }
                const int n = nbase + f * 8 + q2;
                if (WH) {
                    __half2 h = __floats2half2_rn(v0, v1);
                    float2 hf = __half22float2(h);
                    __half2 l = __floats2half2_rn(v0 - hf.x, v1 - hf.y);
                    *(__half2*)(outh  + (size_t)node * DIM + n) = h;
                    *(__half2*)(outlo + (size_t)node * DIM + n) = l;
                } else {
                    *(float2*)(out + (size_t)node * DN + n) = make_float2(v0, v1);
                }
            }
        }
    }
}

// ---------------- host ----------------
extern "C" void kernel_launch(void* const* d_in, const int* in_sizes, int n_in,
                              void* d_out, int out_size) {
    const float* x   = (const float*)d_in[0];
    const int*   ei  = (const int*)d_in[1];
    const float* Wl1 = (const float*)d_in[2];
    const float* Wr1 = (const float*)d_in[3];
    const float* b1  = (const float*)d_in[4];
    const float* Wl2 = (const float*)d_in[5];
    const float* Wr2 = (const float*)d_in[6];
    const float* b2  = (const float*)d_in[7];
    float* out = (float*)d_out;

    const int* src = ei;
    const int* dst = ei + N_EDGES;

    __half *xh, *xlo, *hh, *hlo, *aggh, *wt;
    int* cnt;
    cudaGetSymbolAddress((void**)&xh, g_xh);
    cudaGetSymbolAddress((void**)&xlo, g_xlo);
    cudaGetSymbolAddress((void**)&hh, g_hh);
    cudaGetSymbolAddress((void**)&hlo, g_hlo);
    cudaGetSymbolAddress((void**)&aggh, g_aggh);
    cudaGetSymbolAddress((void**)&wt, g_wt);
    cudaGetSymbolAddress((void**)&cnt, g_count);

    __half* wl1h = wt;          __half* wl1l = wt + 16384;
    __half* wr1h = wt + 32768;  __half* wr1l = wt + 49152;
    __half* wl2h = wt + 65536;  __half* wl2l = wt + 73728;
    __half* wr2h = wt + 81920;  __half* wr2l = wt + 90112;

    const int SMEM1 = 3 * (128 * 40 * 2 + 128 * 40 * 2) + (128 + 128) * 4;  // 62464
    const int SMEM2 = 3 * (128 * 40 * 2 + 64 * 40 * 2) + (64 + 128) * 4;    // 46848
    cudaFuncSetAttribute(k_gemm_mma<128, true, true>,
                         cudaFuncAttributeMaxDynamicSharedMemorySize, SMEM1);
    cudaFuncSetAttribute(k_gemm_mma<64, false, false>,
                         cudaFuncAttributeMaxDynamicSharedMemorySize, SMEM2);

    // prep
    cudaMemsetAsync(cnt, 0, N_NODES * sizeof(int));
    const int n4 = N_NODES * DIM / 4;
    k_xsplit<<<(n4 + 255) / 256, 256>>>(x, xh, xlo, n4);
    k_wprep_all<<<192, 256>>>(Wl1, Wr1, Wl2, Wr2, wt);

    // CSR build (max-aggregation is order-invariant -> deterministic)
    k_hist<<<(N_EDGES + 255) / 256, 256>>>(dst);
    k_bsum<<<SCAN_BLOCKS, 1024>>>();
    k_scanb<<<1, 128>>>();
    k_off<<<SCAN_BLOCKS, 1024>>>();
    k_bin<<<(N_EDGES + 255) / 256, 256>>>(src, dst);

    const int segmax_blocks = (N_NODES * 32 + 255) / 256;
    const int gemm_blocks   = (N_NODES + 127) / 128;   // 782

    // layer 1: C = agg@Wl1h + agg@Wl1l + xh@Wr1h + xh@Wr1l + xlo@Wr1h
    k_segmax_h<<<segmax_blocks, 256>>>(xh, aggh);
    {
        GemmSegs s;
        s.A[0] = aggh; s.W[0] = wl1h;
        s.A[1] = aggh; s.W[1] = wl1l;
        s.A[2] = xh;   s.W[2] = wr1h;
        s.A[3] = xh;   s.W[3] = wr1l;
        s.A[4] = xlo;  s.W[4] = wr1h;
        k_gemm_mma<128, true, true><<<gemm_blocks, 256, SMEM1>>>(s, b1, nullptr, hh, hlo);
    }

    // layer 2
    k_segmax_h<<<segmax_blocks, 256>>>(hh, aggh);
    {
        GemmSegs s;
        s.A[0] = aggh; s.W[0] = wl2h;
        s.A[1] = aggh; s.W[1] = wl2l;
        s.A[2] = hh;   s.W[2] = wr2h;
        s.A[3] = hh;   s.W[3] = wr2l;
        s.A[4] = hlo;  s.W[4] = wr2h;
        k_gemm_mma<64, false, false><<<gemm_blocks, 256, SMEM2>>>(s, b2, out, nullptr, nullptr);
    }
}

// round 14
// speedup vs baseline: 2.7838x; 1.1798x over previous
#include <cuda_runtime.h>
#include <cuda_fp16.h>
#include <math.h>
#include <stdint.h>

#define N_NODES 100000
#define N_EDGES 1600000
#define DIM 128
#define SCAN_BLOCKS 98    // ceil(100000/1024)

// ---------------- device scratch (no allocations allowed) ----------------
__device__ __half g_xh [(size_t)N_NODES * DIM];
__device__ __half g_xlo[(size_t)N_NODES * DIM];
__device__ __half g_hh [(size_t)N_NODES * DIM];
__device__ __half g_hlo[(size_t)N_NODES * DIM];
__device__ __half g_aggh[(size_t)N_NODES * DIM];
__device__ __half g_wt[49152];          // transposed fp16 hi weights [n][k]
__device__ int    g_count[N_NODES];
__device__ int    g_off[N_NODES + 1];
__device__ int    g_cursor[N_NODES];
__device__ int    g_ssrc[N_EDGES];
__device__ int    g_bsum[SCAN_BLOCKS];
__device__ int    g_bpre[SCAN_BLOCKS];

// g_wt layout (all [n][k], k-stride 128):
//  Wl1h:0  Wr1h:16384  Wl2h:32768  Wr2h:40960

// ---------------- helpers ----------------
__device__ __forceinline__ __half2 u2h2(unsigned u) {
    __half2 h; *reinterpret_cast<unsigned*>(&h) = u; return h;
}
__device__ __forceinline__ unsigned h2u2(__half2 h) {
    return *reinterpret_cast<unsigned*>(&h);
}
__device__ __forceinline__ void cp16(uint32_t saddr, const void* gaddr) {
    asm volatile("cp.async.cg.shared.global [%0], [%1], 16;" :: "r"(saddr), "l"(gaddr));
}
__device__ __forceinline__ void cp_commit() {
    asm volatile("cp.async.commit_group;" ::: "memory");
}
template <int N>
__device__ __forceinline__ void cp_wait() {
    asm volatile("cp.async.wait_group %0;" :: "n"(N) : "memory");
}

// ---------------- prep: split fp32 -> fp16 hi + fp16 lo ----------------
__global__ void k_xsplit(const float* __restrict__ x, __half* __restrict__ xh,
                         __half* __restrict__ xlo, int n4) {
    int i = blockIdx.x * blockDim.x + threadIdx.x;
    if (i >= n4) return;
    float4 v = ((const float4*)x)[i];
    __half2 h0 = __floats2half2_rn(v.x, v.y);
    __half2 h1 = __floats2half2_rn(v.z, v.w);
    float2 f0 = __half22float2(h0);
    float2 f1 = __half22float2(h1);
    __half2 l0 = __floats2half2_rn(v.x - f0.x, v.y - f0.y);
    __half2 l1 = __floats2half2_rn(v.z - f1.x, v.w - f1.y);
    ((__half2*)xh)[2 * i] = h0;  ((__half2*)xh)[2 * i + 1] = h1;
    ((__half2*)xlo)[2 * i] = l0; ((__half2*)xlo)[2 * i + 1] = l1;
}

// all 4 weight matrices -> transposed fp16-hi [n][k] in one launch
__global__ void k_wprep_all(const float* __restrict__ Wl1, const float* __restrict__ Wr1,
                            const float* __restrict__ Wl2, const float* __restrict__ Wr2,
                            __half* __restrict__ wt) {
    int i = blockIdx.x * blockDim.x + threadIdx.x;
    if (i >= 49152) return;
    const float* W; int N, hio, li;
    if (i < 16384)      { W = Wl1; N = 128; hio = 0;     li = i; }
    else if (i < 32768) { W = Wr1; N = 128; hio = 16384; li = i - 16384; }
    else if (i < 40960) { W = Wl2; N = 64;  hio = 32768; li = i - 32768; }
    else                { W = Wr2; N = 64;  hio = 40960; li = i - 40960; }
    int k = li / N, n = li % N;
    wt[hio + n * 128 + k] = __float2half_rn(W[li]);
}

// ---------------- CSR build ----------------
__global__ void k_hist(const int* __restrict__ dst) {
    int i = blockIdx.x * blockDim.x + threadIdx.x;
    if (i < N_EDGES) atomicAdd(&g_count[dst[i]], 1);
}

// ---- two-level parallel scan: bsum -> scanb -> off ----
__global__ void k_bsum() {
    __shared__ int wsum[32];
    const int t = threadIdx.x;
    const int i = blockIdx.x * 1024 + t;
    int v = (i < N_NODES) ? g_count[i] : 0;
#pragma unroll
    for (int d = 16; d > 0; d >>= 1) v += __shfl_down_sync(0xffffffffu, v, d);
    if ((t & 31) == 0) wsum[t >> 5] = v;
    __syncthreads();
    if (t < 32) {
        int s = wsum[t];
#pragma unroll
        for (int d = 16; d > 0; d >>= 1) s += __shfl_down_sync(0xffffffffu, s, d);
        if (t == 0) g_bsum[blockIdx.x] = s;
    }
}

__global__ void k_scanb() {
    __shared__ int sh[128];
    const int t = threadIdx.x;
    int v = (t < SCAN_BLOCKS) ? g_bsum[t] : 0;
    sh[t] = v;
    __syncthreads();
    for (int d = 1; d < 128; d <<= 1) {
        int u = (t >= d) ? sh[t - d] : 0;
        __syncthreads();
        sh[t] += u;
        __syncthreads();
    }
    if (t < SCAN_BLOCKS) g_bpre[t] = sh[t] - v;   // exclusive prefix
}

__global__ void k_off() {
    __shared__ int sh[1024];
    const int t = threadIdx.x;
    const int i = blockIdx.x * 1024 + t;
    int v = (i < N_NODES) ? g_count[i] : 0;
    sh[t] = v;
    __syncthreads();
    for (int d = 1; d < 1024; d <<= 1) {
        int u = (t >= d) ? sh[t - d] : 0;
        __syncthreads();
        sh[t] += u;
        __syncthreads();
    }
    if (i < N_NODES) {
        int off = g_bpre[blockIdx.x] + sh[t] - v;  // exclusive
        g_off[i] = off;
        g_cursor[i] = off;
        if (i == N_NODES - 1) g_off[N_NODES] = N_EDGES;
    }
}

__global__ void k_bin(const int* __restrict__ src, const int* __restrict__ dst) {
    int i = blockIdx.x * blockDim.x + threadIdx.x;
    if (i < N_EDGES) {
        int d = dst[i];
        int p = atomicAdd(&g_cursor[d], 1);
        g_ssrc[p] = src[i];
    }
}

// ---------------- segment max (fp16): one warp per node, MLP-4 ----------------
__global__ void k_segmax_h(const __half* __restrict__ feat, __half* __restrict__ agg) {
    int gw = (blockIdx.x * blockDim.x + threadIdx.x) >> 5;
    if (gw >= N_NODES) return;
    const int lane = threadIdx.x & 31;
    const int beg = __ldg(&g_off[gw]);
    const int end = __ldg(&g_off[gw + 1]);
    const unsigned NEGU = 0xFC00FC00u;
    __half2 m0 = u2h2(NEGU), m1 = u2h2(NEGU);
    int e = beg;
    for (; e + 4 <= end; e += 4) {
        int s0 = __ldg(&g_ssrc[e]);
        int s1 = __ldg(&g_ssrc[e + 1]);
        int s2 = __ldg(&g_ssrc[e + 2]);
        int s3 = __ldg(&g_ssrc[e + 3]);
        uint2 v0 = __ldg((const uint2*)(feat + (size_t)s0 * DIM) + lane);
        uint2 v1 = __ldg((const uint2*)(feat + (size_t)s1 * DIM) + lane);
        uint2 v2 = __ldg((const uint2*)(feat + (size_t)s2 * DIM) + lane);
        uint2 v3 = __ldg((const uint2*)(feat + (size_t)s3 * DIM) + lane);
        m0 = __hmax2(__hmax2(__hmax2(m0, u2h2(v0.x)), __hmax2(u2h2(v1.x), u2h2(v2.x))), u2h2(v3.x));
        m1 = __hmax2(__hmax2(__hmax2(m1, u2h2(v0.y)), __hmax2(u2h2(v1.y), u2h2(v2.y))), u2h2(v3.y));
    }
    for (; e < end; e++) {
        int s = __ldg(&g_ssrc[e]);
        uint2 v = __ldg((const uint2*)(feat + (size_t)s * DIM) + lane);
        m0 = __hmax2(m0, u2h2(v.x));
        m1 = __hmax2(m1, u2h2(v.y));
    }
    if (beg == end) { m0 = u2h2(0u); m1 = u2h2(0u); }
    uint2 o; o.x = h2u2(m0); o.y = h2u2(m1);
    ((uint2*)(agg + (size_t)gw * DIM))[lane] = o;
}

// ---------------- HMMA GEMM with cp.async 3-stage pipeline ----------------
// C[128 x DN] = sum over 3 segments: A_seg[128 x 128](fp16) @ W_seg[128 x DN](fp16)
// Segments: aggh@Wl_hi, xh@Wr_hi, xlo@Wr_hi (A-side root compensation; W fp16-hi).
// Warp grid 4(M) x 2(N); warp tile 32 x DN/2. Epilogue: bias + row L2-norm (+relu).
struct GemmSegs { const __half* A[3]; const __half* W[3]; };

template <int DN, bool RELU, bool WH>
__global__ void __launch_bounds__(256, 2)
k_gemm_mma(GemmSegs segs, const float* __restrict__ bias,
           float* __restrict__ out, __half* __restrict__ outh,
           __half* __restrict__ outlo) {
    constexpr int KC   = 32;
    constexpr int AST  = 40;                   // smem k-stride (halfs)
    constexpr int NW   = DN / 2;               // n per warp
    constexpr int NG2  = NW / 16;              // B ldmatrix x4 groups per warp (4 or 2)
    constexpr int NF   = NW / 8;               // n8 frags per warp (8 or 4)
    constexpr int WJ   = DN / 64;              // W cp.async per thread (2 or 1)
    constexpr int NCH  = 12;                   // 3 segments x 4 chunks
    constexpr int STG  = 3;
    constexpr int SA_B = 128 * AST * 2;        // A stage bytes
    constexpr int SW_B = DN * AST * 2;         // W stage bytes

    extern __shared__ unsigned char smem[];
    __half* sA = (__half*)smem;                         // [STG][128*AST]
    __half* sW = (__half*)(smem + STG * SA_B);          // [STG][DN*AST]
    float* sbias = (float*)(smem + STG * (SA_B + SW_B));
    float* sSq   = sbias + DN;

    const int tid  = threadIdx.x;
    const int warp = tid >> 5;
    const int lane = tid & 31;
    const int node0  = blockIdx.x * 128;
    const int mbase  = (warp & 3) * 32;
    const int nbase  = (warp >> 2) * NW;

    if (tid < DN)  sbias[tid] = bias[tid];
    if (tid < 128) sSq[tid] = 0.f;

    const uint32_t saU = (uint32_t)__cvta_generic_to_shared(sA);
    const uint32_t swU = (uint32_t)__cvta_generic_to_shared(sW);

    // cp.async mapping
    const int arow = tid >> 2;                 // A: 2 x 16B per thread (rows 0..127)
    const int ako  = (tid & 3) * 8;
    const size_t agrow = (size_t)min(node0 + arow, N_NODES - 1);

    auto issue = [&](int c) {
        const int seg = c >> 2;
        const int kc  = (c & 3) * KC;
        const int buf = c % STG;
        const __half* Ap = segs.A[seg];
        const __half* Wp = segs.W[seg];
#pragma unroll
        for (int j = 0; j < 2; j++) {
            int row = arow + j * 64;
            cp16(saU + buf * SA_B + (uint32_t)(row * AST + ako) * 2u,
                 Ap + (j ? (size_t)min(node0 + row, N_NODES - 1) : agrow) * DIM + kc + ako);
        }
#pragma unroll
        for (int j = 0; j < WJ; j++) {
            int idx = tid + j * 256;
            int n = idx >> 2, ko = (idx & 3) * 8;
            cp16(swU + buf * SW_B + (uint32_t)(n * AST + ko) * 2u,
                 Wp + n * 128 + kc + ko);
        }
    };

    float acc[2][NF][4];
#pragma unroll
    for (int mf = 0; mf < 2; mf++)
#pragma unroll
        for (int f = 0; f < NF; f++)
#pragma unroll
            for (int j = 0; j < 4; j++) acc[mf][f][j] = 0.f;

    // ldmatrix per-lane offsets
    const int aRow = lane & 15;
    const int aKof = (lane >> 4) << 3;
    const int bNof = (lane & 7) + ((lane >= 16) ? 8 : 0);
    const int bKof = (((lane & 15) >= 8) ? 8 : 0);

    issue(0); cp_commit();
    issue(1); cp_commit();

#pragma unroll 1
    for (int c = 0; c < NCH; c++) {
        cp_wait<1>();
        __syncthreads();
        if (c + 2 < NCH) issue(c + 2);
        cp_commit();                       // empty group ok at tail

        const int buf = c % STG;
        const uint32_t sa = saU + buf * SA_B;
        const uint32_t sw = swU + buf * SW_B;
#pragma unroll
        for (int kk = 0; kk < KC; kk += 16) {
            unsigned a[2][4];
#pragma unroll
            for (int mf = 0; mf < 2; mf++) {
                uint32_t addr = sa + (uint32_t)((mbase + mf * 16 + aRow) * AST + kk + aKof) * 2u;
                asm volatile("ldmatrix.sync.aligned.m8n8.x4.shared.b16 {%0,%1,%2,%3}, [%4];"
                             : "=r"(a[mf][0]), "=r"(a[mf][1]), "=r"(a[mf][2]), "=r"(a[mf][3])
                             : "r"(addr));
            }
#pragma unroll
            for (int g = 0; g < NG2; g++) {
                unsigned b0, b1, b2, b3;
                uint32_t addr = sw + (uint32_t)((nbase + g * 16 + bNof) * AST + kk + bKof) * 2u;
                asm volatile("ldmatrix.sync.aligned.m8n8.x4.shared.b16 {%0,%1,%2,%3}, [%4];"
                             : "=r"(b0), "=r"(b1), "=r"(b2), "=r"(b3) : "r"(addr));
#pragma unroll
                for (int mf = 0; mf < 2; mf++) {
                    asm volatile("mma.sync.aligned.m16n8k16.row.col.f32.f16.f16.f32 "
                                 "{%0,%1,%2,%3},{%4,%5,%6,%7},{%8,%9},{%0,%1,%2,%3};"
                                 : "+f"(acc[mf][2 * g][0]), "+f"(acc[mf][2 * g][1]),
                                   "+f"(acc[mf][2 * g][2]), "+f"(acc[mf][2 * g][3])
                                 : "r"(a[mf][0]), "r"(a[mf][1]), "r"(a[mf][2]), "r"(a[mf][3]),
                                   "r"(b0), "r"(b1));
                    asm volatile("mma.sync.aligned.m16n8k16.row.col.f32.f16.f16.f32 "
                                 "{%0,%1,%2,%3},{%4,%5,%6,%7},{%8,%9},{%0,%1,%2,%3};"
                                 : "+f"(acc[mf][2 * g + 1][0]), "+f"(acc[mf][2 * g + 1][1]),
                                   "+f"(acc[mf][2 * g + 1][2]), "+f"(acc[mf][2 * g + 1][3])
                                 : "r"(a[mf][0]), "r"(a[mf][1]), "r"(a[mf][2]), "r"(a[mf][3]),
                                   "r"(b2), "r"(b3));
                }
            }
        }
        __syncthreads();
    }

    // ---- epilogue: bias, cross-warp row L2-norm via smem, (relu), store
    const int q2 = (lane & 3) * 2;
#pragma unroll
    for (int mf = 0; mf < 2; mf++) {
        float s0 = 0.f, s1 = 0.f;
#pragma unroll
        for (int f = 0; f < NF; f++) {
            float b0 = sbias[nbase + f * 8 + q2];
            float b1 = sbias[nbase + f * 8 + q2 + 1];
            acc[mf][f][0] += b0; acc[mf][f][1] += b1;
            acc[mf][f][2] += b0; acc[mf][f][3] += b1;
            s0 = fmaf(acc[mf][f][0], acc[mf][f][0], fmaf(acc[mf][f][1], acc[mf][f][1], s0));
            s1 = fmaf(acc[mf][f][2], acc[mf][f][2], fmaf(acc[mf][f][3], acc[mf][f][3], s1));
        }
        s0 += __shfl_xor_sync(0xffffffffu, s0, 1);
        s0 += __shfl_xor_sync(0xffffffffu, s0, 2);
        s1 += __shfl_xor_sync(0xffffffffu, s1, 1);
        s1 += __shfl_xor_sync(0xffffffffu, s1, 2);
        if ((lane & 3) == 0) {
            atomicAdd(&sSq[mbase + mf * 16 + (lane >> 2)], s0);
            atomicAdd(&sSq[mbase + mf * 16 + 8 + (lane >> 2)], s1);
        }
    }
    __syncthreads();

#pragma unroll
    for (int mf = 0; mf < 2; mf++) {
#pragma unroll
        for (int half = 0; half < 2; half++) {
            const int lrow = mbase + mf * 16 + half * 8 + (lane >> 2);
            const int node = node0 + lrow;
            if (node >= N_NODES) continue;
            const float inv = 1.f / fmaxf(sqrtf(sSq[lrow]), 1e-12f);
#pragma unroll
            for (int f = 0; f < NF; f++) {
                float v0 = acc[mf][f][2 * half] * inv;
                float v1 = acc[mf][f][2 * half + 1] * inv;
                if (RELU) { v0 = fmaxf(v0, 0.f); v1 = fmaxf(v1, 0.f); }
                const int n = nbase + f * 8 + q2;
                if (WH) {
                    __half2 h = __floats2half2_rn(v0, v1);
                    float2 hf = __half22float2(h);
                    __half2 l = __floats2half2_rn(v0 - hf.x, v1 - hf.y);
                    *(__half2*)(outh  + (size_t)node * DIM + n) = h;
                    *(__half2*)(outlo + (size_t)node * DIM + n) = l;
                } else {
                    *(float2*)(out + (size_t)node * DN + n) = make_float2(v0, v1);
                }
            }
        }
    }
}

// ---------------- host ----------------
extern "C" void kernel_launch(void* const* d_in, const int* in_sizes, int n_in,
                              void* d_out, int out_size) {
    const float* x   = (const float*)d_in[0];
    const int*   ei  = (const int*)d_in[1];
    const float* Wl1 = (const float*)d_in[2];
    const float* Wr1 = (const float*)d_in[3];
    const float* b1  = (const float*)d_in[4];
    const float* Wl2 = (const float*)d_in[5];
    const float* Wr2 = (const float*)d_in[6];
    const float* b2  = (const float*)d_in[7];
    float* out = (float*)d_out;

    const int* src = ei;
    const int* dst = ei + N_EDGES;

    __half *xh, *xlo, *hh, *hlo, *aggh, *wt;
    int* cnt;
    cudaGetSymbolAddress((void**)&xh, g_xh);
    cudaGetSymbolAddress((void**)&xlo, g_xlo);
    cudaGetSymbolAddress((void**)&hh, g_hh);
    cudaGetSymbolAddress((void**)&hlo, g_hlo);
    cudaGetSymbolAddress((void**)&aggh, g_aggh);
    cudaGetSymbolAddress((void**)&wt, g_wt);
    cudaGetSymbolAddress((void**)&cnt, g_count);

    __half* wl1h = wt;           // [128][128]
    __half* wr1h = wt + 16384;   // [128][128]
    __half* wl2h = wt + 32768;   // [64][128]
    __half* wr2h = wt + 40960;   // [64][128]

    const int SMEM1 = 3 * (128 * 40 * 2 + 128 * 40 * 2) + (128 + 128) * 4;  // 62464
    const int SMEM2 = 3 * (128 * 40 * 2 + 64 * 40 * 2) + (64 + 128) * 4;    // 46848
    cudaFuncSetAttribute(k_gemm_mma<128, true, true>,
                         cudaFuncAttributeMaxDynamicSharedMemorySize, SMEM1);
    cudaFuncSetAttribute(k_gemm_mma<64, false, false>,
                         cudaFuncAttributeMaxDynamicSharedMemorySize, SMEM2);

    // prep
    cudaMemsetAsync(cnt, 0, N_NODES * sizeof(int));
    const int n4 = N_NODES * DIM / 4;
    k_xsplit<<<(n4 + 255) / 256, 256>>>(x, xh, xlo, n4);
    k_wprep_all<<<192, 256>>>(Wl1, Wr1, Wl2, Wr2, wt);

    // CSR build (max-aggregation is order-invariant -> deterministic)
    k_hist<<<(N_EDGES + 255) / 256, 256>>>(dst);
    k_bsum<<<SCAN_BLOCKS, 1024>>>();
    k_scanb<<<1, 128>>>();
    k_off<<<SCAN_BLOCKS, 1024>>>();
    k_bin<<<(N_EDGES + 255) / 256, 256>>>(src, dst);

    const int segmax_blocks = (N_NODES * 32 + 255) / 256;
    const int gemm_blocks   = (N_NODES + 127) / 128;   // 782

    // layer 1: C = aggh@Wl1h + xh@Wr1h + xlo@Wr1h
    k_segmax_h<<<segmax_blocks, 256>>>(xh, aggh);
    {
        GemmSegs s;
        s.A[0] = aggh; s.W[0] = wl1h;
        s.A[1] = xh;   s.W[1] = wr1h;
        s.A[2] = xlo;  s.W[2] = wr1h;
        k_gemm_mma<128, true, true><<<gemm_blocks, 256, SMEM1>>>(s, b1, nullptr, hh, hlo);
    }

    // layer 2: C = aggh@Wl2h + hh@Wr2h + hlo@Wr2h
    k_segmax_h<<<segmax_blocks, 256>>>(hh, aggh);
    {
        GemmSegs s;
        s.A[0] = aggh; s.W[0] = wl2h;
        s.A[1] = hh;   s.W[1] = wr2h;
        s.A[2] = hlo;  s.W[2] = wr2h;
        k_gemm_mma<64, false, false><<<gemm_blocks, 256, SMEM2>>>(s, b2, out, nullptr, nullptr);
    }
}

// round 15
// speedup vs baseline: 3.0102x; 1.0813x over previous
#include <cuda_runtime.h>
#include <cuda_fp16.h>
#include <math.h>
#include <stdint.h>

#define N_NODES 100000
#define N_EDGES 1600000
#define DIM 128
#define SCAN_BLOCKS 98    // ceil(100000/1024)

// fused-prep block ranges
#define XSPLIT_BLOCKS 12500   // N_NODES*DIM/4 / 256
#define WPREP_BLOCKS  192
#define HIST_BLOCKS   6250

// ---------------- device scratch (no allocations allowed) ----------------
__device__ __half g_xh [(size_t)N_NODES * DIM];
__device__ __half g_xlo[(size_t)N_NODES * DIM];
__device__ __half g_hh [(size_t)N_NODES * DIM];
__device__ __half g_hlo[(size_t)N_NODES * DIM];
__device__ __half g_aggh[(size_t)N_NODES * DIM];
__device__ __half g_wt[49152];          // transposed fp16 hi weights [n][k]
__device__ int    g_count[N_NODES];
__device__ int    g_off[N_NODES + 1];
__device__ int    g_cursor[N_NODES];
__device__ int    g_ssrc[N_EDGES];
__device__ int    g_bsum[SCAN_BLOCKS];
__device__ int    g_bpre[SCAN_BLOCKS];

// g_wt layout (all [n][k], k-stride 128):
//  Wl1h:0  Wr1h:16384  Wl2h:32768  Wr2h:40960

// ---------------- helpers ----------------
__device__ __forceinline__ __half2 u2h2(unsigned u) {
    __half2 h; *reinterpret_cast<unsigned*>(&h) = u; return h;
}
__device__ __forceinline__ unsigned h2u2(__half2 h) {
    return *reinterpret_cast<unsigned*>(&h);
}
__device__ __forceinline__ void cp16(uint32_t saddr, const void* gaddr) {
    asm volatile("cp.async.cg.shared.global [%0], [%1], 16;" :: "r"(saddr), "l"(gaddr));
}
__device__ __forceinline__ void cp_commit() {
    asm volatile("cp.async.commit_group;" ::: "memory");
}
template <int N>
__device__ __forceinline__ void cp_wait() {
    asm volatile("cp.async.wait_group %0;" :: "n"(N) : "memory");
}

// ---------------- fused prep: xsplit | wprep | hist (independent work) ----------------
__global__ void k_prep(const float* __restrict__ x, __half* __restrict__ xh,
                       __half* __restrict__ xlo,
                       const float* __restrict__ Wl1, const float* __restrict__ Wr1,
                       const float* __restrict__ Wl2, const float* __restrict__ Wr2,
                       __half* __restrict__ wt, const int* __restrict__ dst) {
    const int b = blockIdx.x;
    const int t = threadIdx.x;
    if (b < XSPLIT_BLOCKS) {
        // fp32 -> fp16 hi + lo split, 4 floats per thread
        int i = b * 256 + t;                     // < 3,200,000
        float4 v = ((const float4*)x)[i];
        __half2 h0 = __floats2half2_rn(v.x, v.y);
        __half2 h1 = __floats2half2_rn(v.z, v.w);
        float2 f0 = __half22float2(h0);
        float2 f1 = __half22float2(h1);
        __half2 l0 = __floats2half2_rn(v.x - f0.x, v.y - f0.y);
        __half2 l1 = __floats2half2_rn(v.z - f1.x, v.w - f1.y);
        ((__half2*)xh)[2 * i] = h0;  ((__half2*)xh)[2 * i + 1] = h1;
        ((__half2*)xlo)[2 * i] = l0; ((__half2*)xlo)[2 * i + 1] = l1;
    } else if (b < XSPLIT_BLOCKS + WPREP_BLOCKS) {
        int i = (b - XSPLIT_BLOCKS) * 256 + t;
        if (i < 49152) {
            const float* W; int N, hio, li;
            if (i < 16384)      { W = Wl1; N = 128; hio = 0;     li = i; }
            else if (i < 32768) { W = Wr1; N = 128; hio = 16384; li = i - 16384; }
            else if (i < 40960) { W = Wl2; N = 64;  hio = 32768; li = i - 32768; }
            else                { W = Wr2; N = 64;  hio = 40960; li = i - 40960; }
            int k = li / N, n = li % N;
            wt[hio + n * 128 + k] = __float2half_rn(W[li]);
        }
    } else {
        int i = (b - XSPLIT_BLOCKS - WPREP_BLOCKS) * 256 + t;
        if (i < N_EDGES) atomicAdd(&g_count[dst[i]], 1);
    }
}

// ---- two-level parallel scan: bsum -> scanb -> off ----
__global__ void k_bsum() {
    __shared__ int wsum[32];
    const int t = threadIdx.x;
    const int i = blockIdx.x * 1024 + t;
    int v = (i < N_NODES) ? g_count[i] : 0;
#pragma unroll
    for (int d = 16; d > 0; d >>= 1) v += __shfl_down_sync(0xffffffffu, v, d);
    if ((t & 31) == 0) wsum[t >> 5] = v;
    __syncthreads();
    if (t < 32) {
        int s = wsum[t];
#pragma unroll
        for (int d = 16; d > 0; d >>= 1) s += __shfl_down_sync(0xffffffffu, s, d);
        if (t == 0) g_bsum[blockIdx.x] = s;
    }
}

__global__ void k_scanb() {
    __shared__ int sh[128];
    const int t = threadIdx.x;
    int v = (t < SCAN_BLOCKS) ? g_bsum[t] : 0;
    sh[t] = v;
    __syncthreads();
    for (int d = 1; d < 128; d <<= 1) {
        int u = (t >= d) ? sh[t - d] : 0;
        __syncthreads();
        sh[t] += u;
        __syncthreads();
    }
    if (t < SCAN_BLOCKS) g_bpre[t] = sh[t] - v;   // exclusive prefix
}

__global__ void k_off() {
    __shared__ int sh[1024];
    const int t = threadIdx.x;
    const int i = blockIdx.x * 1024 + t;
    int v = (i < N_NODES) ? g_count[i] : 0;
    sh[t] = v;
    __syncthreads();
    for (int d = 1; d < 1024; d <<= 1) {
        int u = (t >= d) ? sh[t - d] : 0;
        __syncthreads();
        sh[t] += u;
        __syncthreads();
    }
    if (i < N_NODES) {
        int off = g_bpre[blockIdx.x] + sh[t] - v;  // exclusive
        g_off[i] = off;
        g_cursor[i] = off;
        if (i == N_NODES - 1) g_off[N_NODES] = N_EDGES;
    }
}

__global__ void k_bin(const int* __restrict__ src, const int* __restrict__ dst) {
    int i = blockIdx.x * blockDim.x + threadIdx.x;
    if (i < N_EDGES) {
        int d = dst[i];
        int p = atomicAdd(&g_cursor[d], 1);
        g_ssrc[p] = src[i];
    }
}

// ---------------- segment max (fp16): one warp per node, MLP-4 ----------------
__global__ void k_segmax_h(const __half* __restrict__ feat, __half* __restrict__ agg) {
    int gw = (blockIdx.x * blockDim.x + threadIdx.x) >> 5;
    if (gw >= N_NODES) return;
    const int lane = threadIdx.x & 31;
    const int beg = __ldg(&g_off[gw]);
    const int end = __ldg(&g_off[gw + 1]);
    const unsigned NEGU = 0xFC00FC00u;
    __half2 m0 = u2h2(NEGU), m1 = u2h2(NEGU);
    int e = beg;
    for (; e + 4 <= end; e += 4) {
        int s0 = __ldg(&g_ssrc[e]);
        int s1 = __ldg(&g_ssrc[e + 1]);
        int s2 = __ldg(&g_ssrc[e + 2]);
        int s3 = __ldg(&g_ssrc[e + 3]);
        uint2 v0 = __ldg((const uint2*)(feat + (size_t)s0 * DIM) + lane);
        uint2 v1 = __ldg((const uint2*)(feat + (size_t)s1 * DIM) + lane);
        uint2 v2 = __ldg((const uint2*)(feat + (size_t)s2 * DIM) + lane);
        uint2 v3 = __ldg((const uint2*)(feat + (size_t)s3 * DIM) + lane);
        m0 = __hmax2(__hmax2(__hmax2(m0, u2h2(v0.x)), __hmax2(u2h2(v1.x), u2h2(v2.x))), u2h2(v3.x));
        m1 = __hmax2(__hmax2(__hmax2(m1, u2h2(v0.y)), __hmax2(u2h2(v1.y), u2h2(v2.y))), u2h2(v3.y));
    }
    for (; e < end; e++) {
        int s = __ldg(&g_ssrc[e]);
        uint2 v = __ldg((const uint2*)(feat + (size_t)s * DIM) + lane);
        m0 = __hmax2(m0, u2h2(v.x));
        m1 = __hmax2(m1, u2h2(v.y));
    }
    if (beg == end) { m0 = u2h2(0u); m1 = u2h2(0u); }
    uint2 o; o.x = h2u2(m0); o.y = h2u2(m1);
    ((uint2*)(agg + (size_t)gw * DIM))[lane] = o;
}

// ---------------- HMMA GEMM: W resident in smem, KC=64, 2-stage A pipeline ----------------
// C[128 x DN] = aggh@W0 + xh@W1 + xlo@W1  (fp16 in, fp32 accum)
// Warp grid 4(M) x 2(N); warp tile 32 x DN/2. Epilogue: bias + row L2-norm (+relu).
template <int DN, bool RELU, bool WH>
__global__ void __launch_bounds__(256, 2)
k_gemm_mma(const __half* __restrict__ A0, const __half* __restrict__ A1,
           const __half* __restrict__ A2,
           const __half* __restrict__ W0, const __half* __restrict__ W1,
           const float* __restrict__ bias,
           float* __restrict__ out, __half* __restrict__ outh,
           __half* __restrict__ outlo) {
    constexpr int KC    = 64;
    constexpr int AST   = 72;                  // A smem k-stride (halfs), 144B: conflict-free
    constexpr int WST   = 136;                 // W smem k-stride (halfs), 272B: conflict-free
    constexpr int NW    = DN / 2;              // n per warp
    constexpr int NG2   = NW / 16;             // B ldmatrix x4 groups per warp (4 or 2)
    constexpr int NF    = NW / 8;              // n8 frags per warp (8 or 4)
    constexpr int NCH   = 6;                   // 3 segments x 2 chunks
    constexpr int SA_B  = 128 * AST * 2;       // A stage bytes (18432)
    constexpr int WMATB = DN * WST * 2;        // one W matrix bytes

    extern __shared__ unsigned char smem[];
    __half* sW = (__half*)smem;                          // [2][DN*WST]
    __half* sA = (__half*)(smem + 2 * WMATB);            // [2][128*AST]
    float* sbias = (float*)(smem + 2 * WMATB + 2 * SA_B);
    float* sSq   = sbias + DN;

    const int tid  = threadIdx.x;
    const int warp = tid >> 5;
    const int lane = tid & 31;
    const int node0  = blockIdx.x * 128;
    const int mbase  = (warp & 3) * 32;
    const int nbase  = (warp >> 2) * NW;

    if (tid < DN)  sbias[tid] = bias[tid];
    if (tid < 128) sSq[tid] = 0.f;

    const uint32_t swU = (uint32_t)__cvta_generic_to_shared(sW);
    const uint32_t saU = (uint32_t)__cvta_generic_to_shared(sA);

    const __half* As[3] = {A0, A1, A2};

    // A chunk staging: 128 rows x 64 halfs = 1024 x 16B; 4 cp16 per thread
    auto issueA = [&](int c) {
        const __half* Ap = As[c >> 1];
        const int kc = (c & 1) * KC;
        const int buf = c & 1;
#pragma unroll
        for (int j = 0; j < 4; j++) {
            int idx = tid + j * 256;
            int row = idx >> 3, ko = (idx & 7) * 8;
            size_t grow = (size_t)min(node0 + row, N_NODES - 1);
            cp16(saU + buf * SA_B + (uint32_t)(row * AST + ko) * 2u,
                 Ap + grow * DIM + kc + ko);
        }
    };

    // stage both W matrices once: DN*16 x 16B chunks each
    {
        const __half* Ws[2] = {W0, W1};
#pragma unroll
        for (int m = 0; m < 2; m++) {
#pragma unroll
            for (int j = 0; j < DN / 16; j++) {   // DN*16/256 per thread
                int idx = tid + j * 256;
                int n = idx >> 4, ko = (idx & 15) * 8;
                cp16(swU + m * WMATB + (uint32_t)(n * WST + ko) * 2u,
                     Ws[m] + n * 128 + ko);
            }
        }
    }
    issueA(0);
    cp_commit();          // G0 = W(both) + A chunk 0

    float acc[2][NF][4];
#pragma unroll
    for (int mf = 0; mf < 2; mf++)
#pragma unroll
        for (int f = 0; f < NF; f++)
#pragma unroll
            for (int j = 0; j < 4; j++) acc[mf][f][j] = 0.f;

    // ldmatrix per-lane offsets
    const int aRow = lane & 15;
    const int aKof = (lane >> 4) << 3;
    const int bNof = (lane & 7) + ((lane >= 16) ? 8 : 0);
    const int bKof = (((lane & 15) >= 8) ? 8 : 0);

#pragma unroll 1
    for (int c = 0; c < NCH; c++) {
        if (c + 1 < NCH) issueA(c + 1);
        cp_commit();                       // empty at tail is fine
        cp_wait<1>();                      // chunk c (and W) complete
        __syncthreads();

        const uint32_t sa = saU + (c & 1) * SA_B;
        const uint32_t swm = swU + ((c >> 1) ? 1 : 0) * WMATB;   // seg0 -> W0, segs 1,2 -> W1
        const int kc = (c & 1) * KC;
#pragma unroll
        for (int kk = 0; kk < KC; kk += 16) {
            unsigned a[2][4];
#pragma unroll
            for (int mf = 0; mf < 2; mf++) {
                uint32_t addr = sa + (uint32_t)((mbase + mf * 16 + aRow) * AST + kk + aKof) * 2u;
                asm volatile("ldmatrix.sync.aligned.m8n8.x4.shared.b16 {%0,%1,%2,%3}, [%4];"
                             : "=r"(a[mf][0]), "=r"(a[mf][1]), "=r"(a[mf][2]), "=r"(a[mf][3])
                             : "r"(addr));
            }
#pragma unroll
            for (int g = 0; g < NG2; g++) {
                unsigned b0, b1, b2, b3;
                uint32_t addr = swm +
                    (uint32_t)((nbase + g * 16 + bNof) * WST + kc + kk + bKof) * 2u;
                asm volatile("ldmatrix.sync.aligned.m8n8.x4.shared.b16 {%0,%1,%2,%3}, [%4];"
                             : "=r"(b0), "=r"(b1), "=r"(b2), "=r"(b3) : "r"(addr));
#pragma unroll
                for (int mf = 0; mf < 2; mf++) {
                    asm volatile("mma.sync.aligned.m16n8k16.row.col.f32.f16.f16.f32 "
                                 "{%0,%1,%2,%3},{%4,%5,%6,%7},{%8,%9},{%0,%1,%2,%3};"
                                 : "+f"(acc[mf][2 * g][0]), "+f"(acc[mf][2 * g][1]),
                                   "+f"(acc[mf][2 * g][2]), "+f"(acc[mf][2 * g][3])
                                 : "r"(a[mf][0]), "r"(a[mf][1]), "r"(a[mf][2]), "r"(a[mf][3]),
                                   "r"(b0), "r"(b1));
                    asm volatile("mma.sync.aligned.m16n8k16.row.col.f32.f16.f16.f32 "
                                 "{%0,%1,%2,%3},{%4,%5,%6,%7},{%8,%9},{%0,%1,%2,%3};"
                                 : "+f"(acc[mf][2 * g + 1][0]), "+f"(acc[mf][2 * g + 1][1]),
                                   "+f"(acc[mf][2 * g + 1][2]), "+f"(acc[mf][2 * g + 1][3])
                                 : "r"(a[mf][0]), "r"(a[mf][1]), "r"(a[mf][2]), "r"(a[mf][3]),
                                   "r"(b2), "r"(b3));
                }
            }
        }
        __syncthreads();                   // protect A buffer reuse (2-stage)
    }

    // ---- epilogue: bias, cross-warp row L2-norm via smem, (relu), store
    const int q2 = (lane & 3) * 2;
#pragma unroll
    for (int mf = 0; mf < 2; mf++) {
        float s0 = 0.f, s1 = 0.f;
#pragma unroll
        for (int f = 0; f < NF; f++) {
            float b0 = sbias[nbase + f * 8 + q2];
            float b1 = sbias[nbase + f * 8 + q2 + 1];
            acc[mf][f][0] += b0; acc[mf][f][1] += b1;
            acc[mf][f][2] += b0; acc[mf][f][3] += b1;
            s0 = fmaf(acc[mf][f][0], acc[mf][f][0], fmaf(acc[mf][f][1], acc[mf][f][1], s0));
            s1 = fmaf(acc[mf][f][2], acc[mf][f][2], fmaf(acc[mf][f][3], acc[mf][f][3], s1));
        }
        s0 += __shfl_xor_sync(0xffffffffu, s0, 1);
        s0 += __shfl_xor_sync(0xffffffffu, s0, 2);
        s1 += __shfl_xor_sync(0xffffffffu, s1, 1);
        s1 += __shfl_xor_sync(0xffffffffu, s1, 2);
        if ((lane & 3) == 0) {
            atomicAdd(&sSq[mbase + mf * 16 + (lane >> 2)], s0);
            atomicAdd(&sSq[mbase + mf * 16 + 8 + (lane >> 2)], s1);
        }
    }
    __syncthreads();

#pragma unroll
    for (int mf = 0; mf < 2; mf++) {
#pragma unroll
        for (int half = 0; half < 2; half++) {
            const int lrow = mbase + mf * 16 + half * 8 + (lane >> 2);
            const int node = node0 + lrow;
            if (node >= N_NODES) continue;
            const float inv = 1.f / fmaxf(sqrtf(sSq[lrow]), 1e-12f);
#pragma unroll
            for (int f = 0; f < NF; f++) {
                float v0 = acc[mf][f][2 * half] * inv;
                float v1 = acc[mf][f][2 * half + 1] * inv;
                if (RELU) { v0 = fmaxf(v0, 0.f); v1 = fmaxf(v1, 0.f); }
                const int n = nbase + f * 8 + q2;
                if (WH) {
                    __half2 h = __floats2half2_rn(v0, v1);
                    float2 hf = __half22float2(h);
                    __half2 l = __floats2half2_rn(v0 - hf.x, v1 - hf.y);
                    *(__half2*)(outh  + (size_t)node * DIM + n) = h;
                    *(__half2*)(outlo + (size_t)node * DIM + n) = l;
                } else {
                    *(float2*)(out + (size_t)node * DN + n) = make_float2(v0, v1);
                }
            }
        }
    }
}

// ---------------- host ----------------
extern "C" void kernel_launch(void* const* d_in, const int* in_sizes, int n_in,
                              void* d_out, int out_size) {
    const float* x   = (const float*)d_in[0];
    const int*   ei  = (const int*)d_in[1];
    const float* Wl1 = (const float*)d_in[2];
    const float* Wr1 = (const float*)d_in[3];
    const float* b1  = (const float*)d_in[4];
    const float* Wl2 = (const float*)d_in[5];
    const float* Wr2 = (const float*)d_in[6];
    const float* b2  = (const float*)d_in[7];
    float* out = (float*)d_out;

    const int* src = ei;
    const int* dst = ei + N_EDGES;

    __half *xh, *xlo, *hh, *hlo, *aggh, *wt;
    int* cnt;
    cudaGetSymbolAddress((void**)&xh, g_xh);
    cudaGetSymbolAddress((void**)&xlo, g_xlo);
    cudaGetSymbolAddress((void**)&hh, g_hh);
    cudaGetSymbolAddress((void**)&hlo, g_hlo);
    cudaGetSymbolAddress((void**)&aggh, g_aggh);
    cudaGetSymbolAddress((void**)&wt, g_wt);
    cudaGetSymbolAddress((void**)&cnt, g_count);

    __half* wl1h = wt;           // [128][128]
    __half* wr1h = wt + 16384;   // [128][128]
    __half* wl2h = wt + 32768;   // [64][128]
    __half* wr2h = wt + 40960;   // [64][128]

    // smem: 2 W matrices (WST=136) + 2 A stages (AST=72) + bias + ssq
    const int SMEM1 = 2 * (128 * 136 * 2) + 2 * (128 * 72 * 2) + (128 + 128) * 4;  // 107520
    const int SMEM2 = 2 * (64 * 136 * 2)  + 2 * (128 * 72 * 2) + (64 + 128) * 4;   // 72448
    cudaFuncSetAttribute(k_gemm_mma<128, true, true>,
                         cudaFuncAttributeMaxDynamicSharedMemorySize, SMEM1);
    cudaFuncSetAttribute(k_gemm_mma<64, false, false>,
                         cudaFuncAttributeMaxDynamicSharedMemorySize, SMEM2);

    // fused prep: xsplit | wprep | hist  (cnt must be zeroed first)
    cudaMemsetAsync(cnt, 0, N_NODES * sizeof(int));
    k_prep<<<XSPLIT_BLOCKS + WPREP_BLOCKS + HIST_BLOCKS, 256>>>(
        x, xh, xlo, Wl1, Wr1, Wl2, Wr2, wt, dst);

    // CSR build (max-aggregation is order-invariant -> deterministic)
    k_bsum<<<SCAN_BLOCKS, 1024>>>();
    k_scanb<<<1, 128>>>();
    k_off<<<SCAN_BLOCKS, 1024>>>();
    k_bin<<<(N_EDGES + 255) / 256, 256>>>(src, dst);

    const int segmax_blocks = (N_NODES * 32 + 255) / 256;
    const int gemm_blocks   = (N_NODES + 127) / 128;   // 782

    // layer 1: C = aggh@Wl1h + xh@Wr1h + xlo@Wr1h
    k_segmax_h<<<segmax_blocks, 256>>>(xh, aggh);
    k_gemm_mma<128, true, true><<<gemm_blocks, 256, SMEM1>>>(
        aggh, xh, xlo, wl1h, wr1h, b1, nullptr, hh, hlo);

    // layer 2: C = aggh@Wl2h + hh@Wr2h + hlo@Wr2h
    k_segmax_h<<<segmax_blocks, 256>>>(hh, aggh);
    k_gemm_mma<64, false, false><<<gemm_blocks, 256, SMEM2>>>(
        aggh, hh, hlo, wl2h, wr2h, b2, out, nullptr, nullptr);
}

// round 16
// speedup vs baseline: 3.4346x; 1.1410x over previous
#include <cuda_runtime.h>
#include <cuda_fp16.h>
#include <math.h>
#include <stdint.h>

#define N_NODES 100000
#define N_EDGES 1600000
#define DIM 128
#define SCAN_BLOCKS 98    // ceil(100000/1024); <=148 SMs -> co-resident grid barrier is safe

// fused-prep block ranges
#define XSPLIT_BLOCKS 12500   // N_NODES*DIM/4 / 256
#define WPREP_BLOCKS  192
#define HIST_BLOCKS   1563    // 400000 int4-edges / 256
#define BIN_BLOCKS    1563

// ---------------- device scratch (no allocations allowed) ----------------
__device__ __half g_xh [(size_t)N_NODES * DIM];
__device__ __half g_hh [(size_t)N_NODES * DIM];
__device__ __half g_aggh[(size_t)N_NODES * DIM];
__device__ __half g_wt[49152];          // transposed fp16 hi weights [n][k]
__device__ int    g_count[N_NODES];
__device__ int    g_off[N_NODES + 1];
__device__ int    g_cursor[N_NODES];
__device__ int    g_ssrc[N_EDGES];
__device__ int    g_bsum[SCAN_BLOCKS];
__device__ int    g_flag;

// g_wt layout (all [n][k], k-stride 128):
//  Wl1h:0  Wr1h:16384  Wl2h:32768  Wr2h:40960

// ---------------- helpers ----------------
__device__ __forceinline__ __half2 u2h2(unsigned u) {
    __half2 h; *reinterpret_cast<unsigned*>(&h) = u; return h;
}
__device__ __forceinline__ unsigned h2u2(__half2 h) {
    return *reinterpret_cast<unsigned*>(&h);
}
__device__ __forceinline__ void cp16(uint32_t saddr, const void* gaddr) {
    asm volatile("cp.async.cg.shared.global [%0], [%1], 16;" :: "r"(saddr), "l"(gaddr));
}
__device__ __forceinline__ void cp_commit() {
    asm volatile("cp.async.commit_group;" ::: "memory");
}
template <int N>
__device__ __forceinline__ void cp_wait() {
    asm volatile("cp.async.wait_group %0;" :: "n"(N) : "memory");
}

// ---------------- fused prep: xconv | wprep | hist (independent work) ----------------
__global__ void k_prep(const float* __restrict__ x, __half* __restrict__ xh,
                       const float* __restrict__ Wl1, const float* __restrict__ Wr1,
                       const float* __restrict__ Wl2, const float* __restrict__ Wr2,
                       __half* __restrict__ wt, const int* __restrict__ dst) {
    const int b = blockIdx.x;
    const int t = threadIdx.x;
    if (b == 0 && t == 0) g_flag = 0;         // reset scan barrier (runs before k_scan_all)
    if (b < XSPLIT_BLOCKS) {
        int i = b * 256 + t;                  // < 3,200,000 float4s
        float4 v = ((const float4*)x)[i];
        ((__half2*)xh)[2 * i]     = __floats2half2_rn(v.x, v.y);
        ((__half2*)xh)[2 * i + 1] = __floats2half2_rn(v.z, v.w);
    } else if (b < XSPLIT_BLOCKS + WPREP_BLOCKS) {
        int i = (b - XSPLIT_BLOCKS) * 256 + t;
        if (i < 49152) {
            const float* W; int N, hio, li;
            if (i < 16384)      { W = Wl1; N = 128; hio = 0;     li = i; }
            else if (i < 32768) { W = Wr1; N = 128; hio = 16384; li = i - 16384; }
            else if (i < 40960) { W = Wl2; N = 64;  hio = 32768; li = i - 32768; }
            else                { W = Wr2; N = 64;  hio = 40960; li = i - 40960; }
            int k = li / N, n = li % N;
            wt[hio + n * 128 + k] = __float2half_rn(W[li]);
        }
    } else {
        int i = ((b - XSPLIT_BLOCKS - WPREP_BLOCKS) * 256 + t) * 4;   // 4 edges/thread
        if (i < N_EDGES) {
            int4 d4 = *(const int4*)(dst + i);
            atomicAdd(&g_count[d4.x], 1);
            atomicAdd(&g_count[d4.y], 1);
            atomicAdd(&g_count[d4.z], 1);
            atomicAdd(&g_count[d4.w], 1);
        }
    }
}

// ---------------- single-kernel scan with grid flag-barrier (98 co-resident blocks) ----------------
__global__ void k_scan_all() {
    __shared__ int sh[1024];
    __shared__ int red[32];
    __shared__ int bpre;
    const int t = threadIdx.x;
    const int b = blockIdx.x;
    const int i = b * 1024 + t;
    int v = (i < N_NODES) ? g_count[i] : 0;
    sh[t] = v;
    __syncthreads();
    for (int d = 1; d < 1024; d <<= 1) {       // inclusive Hillis-Steele
        int u = (t >= d) ? sh[t - d] : 0;
        __syncthreads();
        sh[t] += u;
        __syncthreads();
    }
    if (t == 1023) {
        g_bsum[b] = sh[1023];
        __threadfence();
        atomicAdd(&g_flag, 1);
    }
    if (t == 0) {
        while (atomicAdd(&g_flag, 0) < SCAN_BLOCKS) { }
    }
    __syncthreads();
    __threadfence();
    // prefix over blocks < b (b <= 97 < 1024 threads)
    int p = (t < b) ? g_bsum[t] : 0;
#pragma unroll
    for (int d = 16; d > 0; d >>= 1) p += __shfl_down_sync(0xffffffffu, p, d);
    if ((t & 31) == 0) red[t >> 5] = p;
    __syncthreads();
    if (t < 32) {
        int s = red[t];
#pragma unroll
        for (int d = 16; d > 0; d >>= 1) s += __shfl_down_sync(0xffffffffu, s, d);
        if (t == 0) bpre = s;
    }
    __syncthreads();
    if (i < N_NODES) {
        int off = bpre + sh[t] - v;            // exclusive
        g_off[i] = off;
        g_cursor[i] = off;
        if (i == N_NODES - 1) g_off[N_NODES] = N_EDGES;
    }
}

// ---------------- binning, 4 edges per thread ----------------
__global__ void k_bin(const int* __restrict__ src, const int* __restrict__ dst) {
    int i = (blockIdx.x * 256 + threadIdx.x) * 4;
    if (i >= N_EDGES) return;
    int4 d4 = *(const int4*)(dst + i);
    int4 s4 = *(const int4*)(src + i);
    int p0 = atomicAdd(&g_cursor[d4.x], 1);
    int p1 = atomicAdd(&g_cursor[d4.y], 1);
    int p2 = atomicAdd(&g_cursor[d4.z], 1);
    int p3 = atomicAdd(&g_cursor[d4.w], 1);
    g_ssrc[p0] = s4.x;
    g_ssrc[p1] = s4.y;
    g_ssrc[p2] = s4.z;
    g_ssrc[p3] = s4.w;
}

// ---------------- segment max (fp16): one warp per node, MLP-4 ----------------
__global__ void k_segmax_h(const __half* __restrict__ feat, __half* __restrict__ agg) {
    int gw = (blockIdx.x * blockDim.x + threadIdx.x) >> 5;
    if (gw >= N_NODES) return;
    const int lane = threadIdx.x & 31;
    const int beg = __ldg(&g_off[gw]);
    const int end = __ldg(&g_off[gw + 1]);
    const unsigned NEGU = 0xFC00FC00u;
    __half2 m0 = u2h2(NEGU), m1 = u2h2(NEGU);
    int e = beg;
    for (; e + 4 <= end; e += 4) {
        int s0 = __ldg(&g_ssrc[e]);
        int s1 = __ldg(&g_ssrc[e + 1]);
        int s2 = __ldg(&g_ssrc[e + 2]);
        int s3 = __ldg(&g_ssrc[e + 3]);
        uint2 v0 = __ldg((const uint2*)(feat + (size_t)s0 * DIM) + lane);
        uint2 v1 = __ldg((const uint2*)(feat + (size_t)s1 * DIM) + lane);
        uint2 v2 = __ldg((const uint2*)(feat + (size_t)s2 * DIM) + lane);
        uint2 v3 = __ldg((const uint2*)(feat + (size_t)s3 * DIM) + lane);
        m0 = __hmax2(__hmax2(__hmax2(m0, u2h2(v0.x)), __hmax2(u2h2(v1.x), u2h2(v2.x))), u2h2(v3.x));
        m1 = __hmax2(__hmax2(__hmax2(m1, u2h2(v0.y)), __hmax2(u2h2(v1.y), u2h2(v2.y))), u2h2(v3.y));
    }
    for (; e < end; e++) {
        int s = __ldg(&g_ssrc[e]);
        uint2 v = __ldg((const uint2*)(feat + (size_t)s * DIM) + lane);
        m0 = __hmax2(m0, u2h2(v.x));
        m1 = __hmax2(m1, u2h2(v.y));
    }
    if (beg == end) { m0 = u2h2(0u); m1 = u2h2(0u); }
    uint2 o; o.x = h2u2(m0); o.y = h2u2(m1);
    ((uint2*)(agg + (size_t)gw * DIM))[lane] = o;
}

// ---------------- HMMA GEMM: W resident, KC=64, 2-stage A pipeline, 2 segments ----------------
// C[128 x DN] = aggh@W0 + xh@W1  (fp16 in, fp32 accum)
// Warp grid 4(M) x 2(N); warp tile 32 x DN/2. Epilogue: bias + row L2-norm (+relu).
template <int DN, bool RELU, bool WH>
__global__ void __launch_bounds__(256, 2)
k_gemm_mma(const __half* __restrict__ A0, const __half* __restrict__ A1,
           const __half* __restrict__ W0, const __half* __restrict__ W1,
           const float* __restrict__ bias,
           float* __restrict__ out, __half* __restrict__ outh) {
    constexpr int KC    = 64;
    constexpr int AST   = 72;                  // A smem k-stride (halfs), 144B: conflict-free
    constexpr int WST   = 136;                 // W smem k-stride (halfs), 272B: conflict-free
    constexpr int NW    = DN / 2;              // n per warp
    constexpr int NG2   = NW / 16;             // B ldmatrix x4 groups per warp (4 or 2)
    constexpr int NF    = NW / 8;              // n8 frags per warp (8 or 4)
    constexpr int NCH   = 4;                   // 2 segments x 2 chunks
    constexpr int SA_B  = 128 * AST * 2;       // A stage bytes (18432)
    constexpr int WMATB = DN * WST * 2;        // one W matrix bytes

    extern __shared__ unsigned char smem[];
    __half* sW = (__half*)smem;                          // [2][DN*WST]
    __half* sA = (__half*)(smem + 2 * WMATB);            // [2][128*AST]
    float* sbias = (float*)(smem + 2 * WMATB + 2 * SA_B);
    float* sSq   = sbias + DN;

    const int tid  = threadIdx.x;
    const int warp = tid >> 5;
    const int lane = tid & 31;
    const int node0  = blockIdx.x * 128;
    const int mbase  = (warp & 3) * 32;
    const int nbase  = (warp >> 2) * NW;

    if (tid < DN)  sbias[tid] = bias[tid];
    if (tid < 128) sSq[tid] = 0.f;

    const uint32_t swU = (uint32_t)__cvta_generic_to_shared(sW);
    const uint32_t saU = (uint32_t)__cvta_generic_to_shared(sA);

    const __half* As[2] = {A0, A1};

    // A chunk staging: 128 rows x 64 halfs = 1024 x 16B; 4 cp16 per thread
    auto issueA = [&](int c) {
        const __half* Ap = As[c >> 1];
        const int kc = (c & 1) * KC;
        const int buf = c & 1;
#pragma unroll
        for (int j = 0; j < 4; j++) {
            int idx = tid + j * 256;
            int row = idx >> 3, ko = (idx & 7) * 8;
            size_t grow = (size_t)min(node0 + row, N_NODES - 1);
            cp16(saU + buf * SA_B + (uint32_t)(row * AST + ko) * 2u,
                 Ap + grow * DIM + kc + ko);
        }
    };

    // stage both W matrices once: DN*16 x 16B chunks each
    {
        const __half* Ws[2] = {W0, W1};
#pragma unroll
        for (int m = 0; m < 2; m++) {
#pragma unroll
            for (int j = 0; j < DN / 16; j++) {
                int idx = tid + j * 256;
                int n = idx >> 4, ko = (idx & 15) * 8;
                cp16(swU + m * WMATB + (uint32_t)(n * WST + ko) * 2u,
                     Ws[m] + n * 128 + ko);
            }
        }
    }
    issueA(0);
    cp_commit();          // G0 = W(both) + A chunk 0

    float acc[2][NF][4];
#pragma unroll
    for (int mf = 0; mf < 2; mf++)
#pragma unroll
        for (int f = 0; f < NF; f++)
#pragma unroll
            for (int j = 0; j < 4; j++) acc[mf][f][j] = 0.f;

    // ldmatrix per-lane offsets
    const int aRow = lane & 15;
    const int aKof = (lane >> 4) << 3;
    const int bNof = (lane & 7) + ((lane >= 16) ? 8 : 0);
    const int bKof = (((lane & 15) >= 8) ? 8 : 0);

#pragma unroll 1
    for (int c = 0; c < NCH; c++) {
        if (c + 1 < NCH) issueA(c + 1);
        cp_commit();                       // empty at tail is fine
        cp_wait<1>();                      // chunk c (and W) complete
        __syncthreads();

        const uint32_t sa = saU + (c & 1) * SA_B;
        const uint32_t swm = swU + (c >> 1) * WMATB;   // chunks 0,1 -> W0; 2,3 -> W1
        const int kc = (c & 1) * KC;
#pragma unroll
        for (int kk = 0; kk < KC; kk += 16) {
            unsigned a[2][4];
#pragma unroll
            for (int mf = 0; mf < 2; mf++) {
                uint32_t addr = sa + (uint32_t)((mbase + mf * 16 + aRow) * AST + kk + aKof) * 2u;
                asm volatile("ldmatrix.sync.aligned.m8n8.x4.shared.b16 {%0,%1,%2,%3}, [%4];"
                             : "=r"(a[mf][0]), "=r"(a[mf][1]), "=r"(a[mf][2]), "=r"(a[mf][3])
                             : "r"(addr));
            }
#pragma unroll
            for (int g = 0; g < NG2; g++) {
                unsigned b0, b1, b2, b3;
                uint32_t addr = swm +
                    (uint32_t)((nbase + g * 16 + bNof) * WST + kc + kk + bKof) * 2u;
                asm volatile("ldmatrix.sync.aligned.m8n8.x4.shared.b16 {%0,%1,%2,%3}, [%4];"
                             : "=r"(b0), "=r"(b1), "=r"(b2), "=r"(b3) : "r"(addr));
#pragma unroll
                for (int mf = 0; mf < 2; mf++) {
                    asm volatile("mma.sync.aligned.m16n8k16.row.col.f32.f16.f16.f32 "
                                 "{%0,%1,%2,%3},{%4,%5,%6,%7},{%8,%9},{%0,%1,%2,%3};"
                                 : "+f"(acc[mf][2 * g][0]), "+f"(acc[mf][2 * g][1]),
                                   "+f"(acc[mf][2 * g][2]), "+f"(acc[mf][2 * g][3])
                                 : "r"(a[mf][0]), "r"(a[mf][1]), "r"(a[mf][2]), "r"(a[mf][3]),
                                   "r"(b0), "r"(b1));
                    asm volatile("mma.sync.aligned.m16n8k16.row.col.f32.f16.f16.f32 "
                                 "{%0,%1,%2,%3},{%4,%5,%6,%7},{%8,%9},{%0,%1,%2,%3};"
                                 : "+f"(acc[mf][2 * g + 1][0]), "+f"(acc[mf][2 * g + 1][1]),
                                   "+f"(acc[mf][2 * g + 1][2]), "+f"(acc[mf][2 * g + 1][3])
                                 : "r"(a[mf][0]), "r"(a[mf][1]), "r"(a[mf][2]), "r"(a[mf][3]),
                                   "r"(b2), "r"(b3));
                }
            }
        }
        __syncthreads();                   // protect A buffer reuse (2-stage)
    }

    // ---- epilogue: bias, cross-warp row L2-norm via smem, (relu), store
    const int q2 = (lane & 3) * 2;
#pragma unroll
    for (int mf = 0; mf < 2; mf++) {
        float s0 = 0.f, s1 = 0.f;
#pragma unroll
        for (int f = 0; f < NF; f++) {
            float b0 = sbias[nbase + f * 8 + q2];
            float b1 = sbias[nbase + f * 8 + q2 + 1];
            acc[mf][f][0] += b0; acc[mf][f][1] += b1;
            acc[mf][f][2] += b0; acc[mf][f][3] += b1;
            s0 = fmaf(acc[mf][f][0], acc[mf][f][0], fmaf(acc[mf][f][1], acc[mf][f][1], s0));
            s1 = fmaf(acc[mf][f][2], acc[mf][f][2], fmaf(acc[mf][f][3], acc[mf][f][3], s1));
        }
        s0 += __shfl_xor_sync(0xffffffffu, s0, 1);
        s0 += __shfl_xor_sync(0xffffffffu, s0, 2);
        s1 += __shfl_xor_sync(0xffffffffu, s1, 1);
        s1 += __shfl_xor_sync(0xffffffffu, s1, 2);
        if ((lane & 3) == 0) {
            atomicAdd(&sSq[mbase + mf * 16 + (lane >> 2)], s0);
            atomicAdd(&sSq[mbase + mf * 16 + 8 + (lane >> 2)], s1);
        }
    }
    __syncthreads();

#pragma unroll
    for (int mf = 0; mf < 2; mf++) {
#pragma unroll
        for (int half = 0; half < 2; half++) {
            const int lrow = mbase + mf * 16 + half * 8 + (lane >> 2);
            const int node = node0 + lrow;
            if (node >= N_NODES) continue;
            const float inv = 1.f / fmaxf(sqrtf(sSq[lrow]), 1e-12f);
#pragma unroll
            for (int f = 0; f < NF; f++) {
                float v0 = acc[mf][f][2 * half] * inv;
                float v1 = acc[mf][f][2 * half + 1] * inv;
                if (RELU) { v0 = fmaxf(v0, 0.f); v1 = fmaxf(v1, 0.f); }
                const int n = nbase + f * 8 + q2;
                if (WH) {
                    *(__half2*)(outh + (size_t)node * DIM + n) = __floats2half2_rn(v0, v1);
                } else {
                    *(float2*)(out + (size_t)node * DN + n) = make_float2(v0, v1);
                }
            }
        }
    }
}

// ---------------- host ----------------
extern "C" void kernel_launch(void* const* d_in, const int* in_sizes, int n_in,
                              void* d_out, int out_size) {
    const float* x   = (const float*)d_in[0];
    const int*   ei  = (const int*)d_in[1];
    const float* Wl1 = (const float*)d_in[2];
    const float* Wr1 = (const float*)d_in[3];
    const float* b1  = (const float*)d_in[4];
    const float* Wl2 = (const float*)d_in[5];
    const float* Wr2 = (const float*)d_in[6];
    const float* b2  = (const float*)d_in[7];
    float* out = (float*)d_out;

    const int* src = ei;
    const int* dst = ei + N_EDGES;

    __half *xh, *hh, *aggh, *wt;
    int* cnt;
    cudaGetSymbolAddress((void**)&xh, g_xh);
    cudaGetSymbolAddress((void**)&hh, g_hh);
    cudaGetSymbolAddress((void**)&aggh, g_aggh);
    cudaGetSymbolAddress((void**)&wt, g_wt);
    cudaGetSymbolAddress((void**)&cnt, g_count);

    __half* wl1h = wt;           // [128][128]
    __half* wr1h = wt + 16384;   // [128][128]
    __half* wl2h = wt + 32768;   // [64][128]
    __half* wr2h = wt + 40960;   // [64][128]

    // smem: 2 W matrices (WST=136) + 2 A stages (AST=72) + bias + ssq
    const int SMEM1 = 2 * (128 * 136 * 2) + 2 * (128 * 72 * 2) + (128 + 128) * 4;  // 107520
    const int SMEM2 = 2 * (64 * 136 * 2)  + 2 * (128 * 72 * 2) + (64 + 128) * 4;   // 72448
    cudaFuncSetAttribute(k_gemm_mma<128, true, true>,
                         cudaFuncAttributeMaxDynamicSharedMemorySize, SMEM1);
    cudaFuncSetAttribute(k_gemm_mma<64, false, false>,
                         cudaFuncAttributeMaxDynamicSharedMemorySize, SMEM2);

    // fused prep: xconv | wprep | hist (cnt zeroed first; also resets scan flag)
    cudaMemsetAsync(cnt, 0, N_NODES * sizeof(int));
    k_prep<<<XSPLIT_BLOCKS + WPREP_BLOCKS + HIST_BLOCKS, 256>>>(
        x, xh, Wl1, Wr1, Wl2, Wr2, wt, dst);

    // CSR build (max-aggregation is order-invariant -> deterministic)
    k_scan_all<<<SCAN_BLOCKS, 1024>>>();
    k_bin<<<BIN_BLOCKS, 256>>>(src, dst);

    const int segmax_blocks = (N_NODES * 32 + 255) / 256;
    const int gemm_blocks   = (N_NODES + 127) / 128;   // 782

    // layer 1: C = aggh@Wl1h + xh@Wr1h
    k_segmax_h<<<segmax_blocks, 256>>>(xh, aggh);
    k_gemm_mma<128, true, true><<<gemm_blocks, 256, SMEM1>>>(
        aggh, xh, wl1h, wr1h, b1, nullptr, hh);

    // layer 2: C = aggh@Wl2h + hh@Wr2h
    k_segmax_h<<<segmax_blocks, 256>>>(hh, aggh);
    k_gemm_mma<64, false, false><<<gemm_blocks, 256, SMEM2>>>(
        aggh, hh, wl2h, wr2h, b2, out, nullptr);
}

// round 17
// speedup vs baseline: 3.6453x; 1.0614x over previous
#include <cuda_runtime.h>
#include <cuda_fp16.h>
#include <math.h>
#include <stdint.h>

#define N_NODES 100000
#define N_EDGES 1600000
#define DIM 128
#define SCAN_BLOCKS 98    // ceil(100000/1024); <=148 SMs -> co-resident grid barrier is safe

// fused-prep block ranges
#define XSPLIT_BLOCKS 12500   // N_NODES*DIM/4 / 256
#define WPREP_BLOCKS  192
#define HIST_BLOCKS   1563    // 400000 int4-edges / 256

// ---------------- device scratch (no allocations allowed) ----------------
__device__ __half g_xh [(size_t)N_NODES * DIM];
__device__ __half g_hh [(size_t)N_NODES * DIM];
__device__ __half g_aggh[(size_t)N_NODES * DIM];
__device__ __half g_wt[49152];          // transposed fp16 hi weights [n][k]
__device__ int    g_count[N_NODES];
__device__ int    g_off[N_NODES + 1];
__device__ int    g_cursor[N_NODES];
__device__ int    g_ssrc[N_EDGES];
__device__ int    g_bsum[SCAN_BLOCKS];
__device__ int    g_flag;

// g_wt layout (all [n][k], k-stride 128):
//  Wl1h:0  Wr1h:16384  Wl2h:32768  Wr2h:40960

// ---------------- helpers ----------------
__device__ __forceinline__ __half2 u2h2(unsigned u) {
    __half2 h; *reinterpret_cast<unsigned*>(&h) = u; return h;
}
__device__ __forceinline__ unsigned h2u2(__half2 h) {
    return *reinterpret_cast<unsigned*>(&h);
}
__device__ __forceinline__ void cp16(uint32_t saddr, const void* gaddr) {
    asm volatile("cp.async.cg.shared.global [%0], [%1], 16;" :: "r"(saddr), "l"(gaddr));
}
__device__ __forceinline__ void cp_commit() {
    asm volatile("cp.async.commit_group;" ::: "memory");
}
template <int N>
__device__ __forceinline__ void cp_wait() {
    asm volatile("cp.async.wait_group %0;" :: "n"(N) : "memory");
}

// ---------------- fused prep: xconv | wprep | hist (independent work) ----------------
__global__ void k_prep(const float* __restrict__ x, __half* __restrict__ xh,
                       const float* __restrict__ Wl1, const float* __restrict__ Wr1,
                       const float* __restrict__ Wl2, const float* __restrict__ Wr2,
                       __half* __restrict__ wt, const int* __restrict__ dst) {
    const int b = blockIdx.x;
    const int t = threadIdx.x;
    if (b == 0 && t == 0) g_flag = 0;         // reset scan barrier (runs before k_scan_bin)
    if (b < XSPLIT_BLOCKS) {
        int i = b * 256 + t;                  // < 3,200,000 float4s
        float4 v = ((const float4*)x)[i];
        ((__half2*)xh)[2 * i]     = __floats2half2_rn(v.x, v.y);
        ((__half2*)xh)[2 * i + 1] = __floats2half2_rn(v.z, v.w);
    } else if (b < XSPLIT_BLOCKS + WPREP_BLOCKS) {
        int i = (b - XSPLIT_BLOCKS) * 256 + t;
        if (i < 49152) {
            const float* W; int N, hio, li;
            if (i < 16384)      { W = Wl1; N = 128; hio = 0;     li = i; }
            else if (i < 32768) { W = Wr1; N = 128; hio = 16384; li = i - 16384; }
            else if (i < 40960) { W = Wl2; N = 64;  hio = 32768; li = i - 32768; }
            else                { W = Wr2; N = 64;  hio = 40960; li = i - 40960; }
            int k = li / N, n = li % N;
            wt[hio + n * 128 + k] = __float2half_rn(W[li]);
        }
    } else {
        int i = ((b - XSPLIT_BLOCKS - WPREP_BLOCKS) * 256 + t) * 4;   // 4 edges/thread
        if (i < N_EDGES) {
            int4 d4 = *(const int4*)(dst + i);
            atomicAdd(&g_count[d4.x], 1);
            atomicAdd(&g_count[d4.y], 1);
            atomicAdd(&g_count[d4.z], 1);
            atomicAdd(&g_count[d4.w], 1);
        }
    }
}

// ---------------- fused scan + bin: one kernel, two grid flag-barriers ----------------
__global__ void k_scan_bin(const int* __restrict__ src, const int* __restrict__ dst) {
    __shared__ int sh[1024];
    __shared__ int red[32];
    __shared__ int bpre;
    const int t = threadIdx.x;
    const int b = blockIdx.x;
    const int i = b * 1024 + t;

    // ---- phase 1: per-block inclusive scan + publish block sums
    int v = (i < N_NODES) ? g_count[i] : 0;
    sh[t] = v;
    __syncthreads();
    for (int d = 1; d < 1024; d <<= 1) {
        int u = (t >= d) ? sh[t - d] : 0;
        __syncthreads();
        sh[t] += u;
        __syncthreads();
    }
    if (t == 1023) {
        g_bsum[b] = sh[1023];
        __threadfence();
        atomicAdd(&g_flag, 1);
    }
    if (t == 0) {
        while (atomicAdd(&g_flag, 0) < SCAN_BLOCKS) { }
    }
    __syncthreads();
    __threadfence();

    // ---- block prefix over blocks < b
    int p = (t < b) ? g_bsum[t] : 0;
#pragma unroll
    for (int d = 16; d > 0; d >>= 1) p += __shfl_down_sync(0xffffffffu, p, d);
    if ((t & 31) == 0) red[t >> 5] = p;
    __syncthreads();
    if (t < 32) {
        int s = red[t];
#pragma unroll
        for (int d = 16; d > 0; d >>= 1) s += __shfl_down_sync(0xffffffffu, s, d);
        if (t == 0) bpre = s;
    }
    __syncthreads();
    if (i < N_NODES) {
        int off = bpre + sh[t] - v;            // exclusive
        g_off[i] = off;
        g_cursor[i] = off;
        if (i == N_NODES - 1) g_off[N_NODES] = N_EDGES;
    }

    // ---- barrier 2: all cursors visible before binning
    __threadfence();
    __syncthreads();
    if (t == 0) {
        atomicAdd(&g_flag, 1);
        while (atomicAdd(&g_flag, 0) < 2 * SCAN_BLOCKS) { }
    }
    __syncthreads();
    __threadfence();

    // ---- phase 2: bin edges (grid-stride over int4 groups)
    const int gid = b * 1024 + t;
    for (int j = gid; j < N_EDGES / 4; j += SCAN_BLOCKS * 1024) {
        int4 d4 = *(const int4*)(dst + j * 4);
        int4 s4 = *(const int4*)(src + j * 4);
        int p0 = atomicAdd(&g_cursor[d4.x], 1);
        int p1 = atomicAdd(&g_cursor[d4.y], 1);
        int p2 = atomicAdd(&g_cursor[d4.z], 1);
        int p3 = atomicAdd(&g_cursor[d4.w], 1);
        g_ssrc[p0] = s4.x;
        g_ssrc[p1] = s4.y;
        g_ssrc[p2] = s4.z;
        g_ssrc[p3] = s4.w;
    }
}

// ---------------- segment max (fp16): 16 lanes per node, uint4 rows, MLP-4 ----------------
__global__ void k_segmax_h(const __half* __restrict__ feat, __half* __restrict__ agg) {
    int g = (blockIdx.x * 256 + threadIdx.x) >> 4;
    if (g >= N_NODES) return;
    const int l = threadIdx.x & 15;
    const int beg = __ldg(&g_off[g]);
    const int end = __ldg(&g_off[g + 1]);
    const unsigned NEGU = 0xFC00FC00u;
    __half2 m0 = u2h2(NEGU), m1 = m0, m2 = m0, m3 = m0;
    int e = beg;
    for (; e + 4 <= end; e += 4) {
        int s0 = __ldg(&g_ssrc[e]);
        int s1 = __ldg(&g_ssrc[e + 1]);
        int s2 = __ldg(&g_ssrc[e + 2]);
        int s3 = __ldg(&g_ssrc[e + 3]);
        uint4 v0 = __ldg((const uint4*)(feat + (size_t)s0 * DIM) + l);
        uint4 v1 = __ldg((const uint4*)(feat + (size_t)s1 * DIM) + l);
        uint4 v2 = __ldg((const uint4*)(feat + (size_t)s2 * DIM) + l);
        uint4 v3 = __ldg((const uint4*)(feat + (size_t)s3 * DIM) + l);
        m0 = __hmax2(__hmax2(__hmax2(m0, u2h2(v0.x)), __hmax2(u2h2(v1.x), u2h2(v2.x))), u2h2(v3.x));
        m1 = __hmax2(__hmax2(__hmax2(m1, u2h2(v0.y)), __hmax2(u2h2(v1.y), u2h2(v2.y))), u2h2(v3.y));
        m2 = __hmax2(__hmax2(__hmax2(m2, u2h2(v0.z)), __hmax2(u2h2(v1.z), u2h2(v2.z))), u2h2(v3.z));
        m3 = __hmax2(__hmax2(__hmax2(m3, u2h2(v0.w)), __hmax2(u2h2(v1.w), u2h2(v2.w))), u2h2(v3.w));
    }
    for (; e < end; e++) {
        int s = __ldg(&g_ssrc[e]);
        uint4 v = __ldg((const uint4*)(feat + (size_t)s * DIM) + l);
        m0 = __hmax2(m0, u2h2(v.x));
        m1 = __hmax2(m1, u2h2(v.y));
        m2 = __hmax2(m2, u2h2(v.z));
        m3 = __hmax2(m3, u2h2(v.w));
    }
    if (beg == end) { m0 = u2h2(0u); m1 = m0; m2 = m0; m3 = m0; }
    uint4 o;
    o.x = h2u2(m0); o.y = h2u2(m1); o.z = h2u2(m2); o.w = h2u2(m3);
    ((uint4*)(agg + (size_t)g * DIM))[l] = o;
}

// ---------------- HMMA GEMM: W resident, KC=64, 2-stage A pipeline, 2 segments ----------------
// C[128 x DN] = aggh@W0 + xh@W1  (fp16 in, fp32 accum)
// Warp grid 4(M) x 2(N); warp tile 32 x DN/2. Epilogue: bias + row L2-norm (+relu).
template <int DN, bool RELU, bool WH>
__global__ void __launch_bounds__(256, 2)
k_gemm_mma(const __half* __restrict__ A0, const __half* __restrict__ A1,
           const __half* __restrict__ W0, const __half* __restrict__ W1,
           const float* __restrict__ bias,
           float* __restrict__ out, __half* __restrict__ outh) {
    constexpr int KC    = 64;
    constexpr int AST   = 72;                  // A smem k-stride (halfs), 144B: conflict-free
    constexpr int WST   = 136;                 // W smem k-stride (halfs), 272B: conflict-free
    constexpr int NW    = DN / 2;              // n per warp
    constexpr int NG2   = NW / 16;             // B ldmatrix x4 groups per warp (4 or 2)
    constexpr int NF    = NW / 8;              // n8 frags per warp (8 or 4)
    constexpr int NCH   = 4;                   // 2 segments x 2 chunks
    constexpr int SA_B  = 128 * AST * 2;       // A stage bytes (18432)
    constexpr int WMATB = DN * WST * 2;        // one W matrix bytes

    extern __shared__ unsigned char smem[];
    __half* sW = (__half*)smem;                          // [2][DN*WST]
    __half* sA = (__half*)(smem + 2 * WMATB);            // [2][128*AST]
    float* sbias = (float*)(smem + 2 * WMATB + 2 * SA_B);
    float* sSq   = sbias + DN;

    const int tid  = threadIdx.x;
    const int warp = tid >> 5;
    const int lane = tid & 31;
    const int node0  = blockIdx.x * 128;
    const int mbase  = (warp & 3) * 32;
    const int nbase  = (warp >> 2) * NW;

    if (tid < DN)  sbias[tid] = bias[tid];
    if (tid < 128) sSq[tid] = 0.f;

    const uint32_t swU = (uint32_t)__cvta_generic_to_shared(sW);
    const uint32_t saU = (uint32_t)__cvta_generic_to_shared(sA);

    const __half* As[2] = {A0, A1};

    // A chunk staging: 128 rows x 64 halfs = 1024 x 16B; 4 cp16 per thread
    auto issueA = [&](int c) {
        const __half* Ap = As[c >> 1];
        const int kc = (c & 1) * KC;
        const int buf = c & 1;
#pragma unroll
        for (int j = 0; j < 4; j++) {
            int idx = tid + j * 256;
            int row = idx >> 3, ko = (idx & 7) * 8;
            size_t grow = (size_t)min(node0 + row, N_NODES - 1);
            cp16(saU + buf * SA_B + (uint32_t)(row * AST + ko) * 2u,
                 Ap + grow * DIM + kc + ko);
        }
    };

    // stage both W matrices once: DN*16 x 16B chunks each
    {
        const __half* Ws[2] = {W0, W1};
#pragma unroll
        for (int m = 0; m < 2; m++) {
#pragma unroll
            for (int j = 0; j < DN / 16; j++) {
                int idx = tid + j * 256;
                int n = idx >> 4, ko = (idx & 15) * 8;
                cp16(swU + m * WMATB + (uint32_t)(n * WST + ko) * 2u,
                     Ws[m] + n * 128 + ko);
            }
        }
    }
    issueA(0);
    cp_commit();          // G0 = W(both) + A chunk 0

    float acc[2][NF][4];
#pragma unroll
    for (int mf = 0; mf < 2; mf++)
#pragma unroll
        for (int f = 0; f < NF; f++)
#pragma unroll
            for (int j = 0; j < 4; j++) acc[mf][f][j] = 0.f;

    // ldmatrix per-lane offsets
    const int aRow = lane & 15;
    const int aKof = (lane >> 4) << 3;
    const int bNof = (lane & 7) + ((lane >= 16) ? 8 : 0);
    const int bKof = (((lane & 15) >= 8) ? 8 : 0);

#pragma unroll 1
    for (int c = 0; c < NCH; c++) {
        if (c + 1 < NCH) issueA(c + 1);
        cp_commit();                       // empty at tail is fine
        cp_wait<1>();                      // chunk c (and W) complete
        __syncthreads();

        const uint32_t sa = saU + (c & 1) * SA_B;
        const uint32_t swm = swU + (c >> 1) * WMATB;   // chunks 0,1 -> W0; 2,3 -> W1
        const int kc = (c & 1) * KC;
#pragma unroll
        for (int kk = 0; kk < KC; kk += 16) {
            unsigned a[2][4];
#pragma unroll
            for (int mf = 0; mf < 2; mf++) {
                uint32_t addr = sa + (uint32_t)((mbase + mf * 16 + aRow) * AST + kk + aKof) * 2u;
                asm volatile("ldmatrix.sync.aligned.m8n8.x4.shared.b16 {%0,%1,%2,%3}, [%4];"
                             : "=r"(a[mf][0]), "=r"(a[mf][1]), "=r"(a[mf][2]), "=r"(a[mf][3])
                             : "r"(addr));
            }
#pragma unroll
            for (int g = 0; g < NG2; g++) {
                unsigned b0, b1, b2, b3;
                uint32_t addr = swm +
                    (uint32_t)((nbase + g * 16 + bNof) * WST + kc + kk + bKof) * 2u;
                asm volatile("ldmatrix.sync.aligned.m8n8.x4.shared.b16 {%0,%1,%2,%3}, [%4];"
                             : "=r"(b0), "=r"(b1), "=r"(b2), "=r"(b3) : "r"(addr));
#pragma unroll
                for (int mf = 0; mf < 2; mf++) {
                    asm volatile("mma.sync.aligned.m16n8k16.row.col.f32.f16.f16.f32 "
                                 "{%0,%1,%2,%3},{%4,%5,%6,%7},{%8,%9},{%0,%1,%2,%3};"
                                 : "+f"(acc[mf][2 * g][0]), "+f"(acc[mf][2 * g][1]),
                                   "+f"(acc[mf][2 * g][2]), "+f"(acc[mf][2 * g][3])
                                 : "r"(a[mf][0]), "r"(a[mf][1]), "r"(a[mf][2]), "r"(a[mf][3]),
                                   "r"(b0), "r"(b1));
                    asm volatile("mma.sync.aligned.m16n8k16.row.col.f32.f16.f16.f32 "
                                 "{%0,%1,%2,%3},{%4,%5,%6,%7},{%8,%9},{%0,%1,%2,%3};"
                                 : "+f"(acc[mf][2 * g + 1][0]), "+f"(acc[mf][2 * g + 1][1]),
                                   "+f"(acc[mf][2 * g + 1][2]), "+f"(acc[mf][2 * g + 1][3])
                                 : "r"(a[mf][0]), "r"(a[mf][1]), "r"(a[mf][2]), "r"(a[mf][3]),
                                   "r"(b2), "r"(b3));
                }
            }
        }
        __syncthreads();                   // protect A buffer reuse (2-stage)
    }

    // ---- epilogue: bias, cross-warp row L2-norm via smem, (relu), store
    const int q2 = (lane & 3) * 2;
#pragma unroll
    for (int mf = 0; mf < 2; mf++) {
        float s0 = 0.f, s1 = 0.f;
#pragma unroll
        for (int f = 0; f < NF; f++) {
            float b0 = sbias[nbase + f * 8 + q2];
            float b1 = sbias[nbase + f * 8 + q2 + 1];
            acc[mf][f][0] += b0; acc[mf][f][1] += b1;
            acc[mf][f][2] += b0; acc[mf][f][3] += b1;
            s0 = fmaf(acc[mf][f][0], acc[mf][f][0], fmaf(acc[mf][f][1], acc[mf][f][1], s0));
            s1 = fmaf(acc[mf][f][2], acc[mf][f][2], fmaf(acc[mf][f][3], acc[mf][f][3], s1));
        }
        s0 += __shfl_xor_sync(0xffffffffu, s0, 1);
        s0 += __shfl_xor_sync(0xffffffffu, s0, 2);
        s1 += __shfl_xor_sync(0xffffffffu, s1, 1);
        s1 += __shfl_xor_sync(0xffffffffu, s1, 2);
        if ((lane & 3) == 0) {
            atomicAdd(&sSq[mbase + mf * 16 + (lane >> 2)], s0);
            atomicAdd(&sSq[mbase + mf * 16 + 8 + (lane >> 2)], s1);
        }
    }
    __syncthreads();

#pragma unroll
    for (int mf = 0; mf < 2; mf++) {
#pragma unroll
        for (int half = 0; half < 2; half++) {
            const int lrow = mbase + mf * 16 + half * 8 + (lane >> 2);
            const int node = node0 + lrow;
            if (node >= N_NODES) continue;
            const float inv = 1.f / fmaxf(sqrtf(sSq[lrow]), 1e-12f);
#pragma unroll
            for (int f = 0; f < NF; f++) {
                float v0 = acc[mf][f][2 * half] * inv;
                float v1 = acc[mf][f][2 * half + 1] * inv;
                if (RELU) { v0 = fmaxf(v0, 0.f); v1 = fmaxf(v1, 0.f); }
                const int n = nbase + f * 8 + q2;
                if (WH) {
                    *(__half2*)(outh + (size_t)node * DIM + n) = __floats2half2_rn(v0, v1);
                } else {
                    *(float2*)(out + (size_t)node * DN + n) = make_float2(v0, v1);
                }
            }
        }
    }
}

// ---------------- host ----------------
extern "C" void kernel_launch(void* const* d_in, const int* in_sizes, int n_in,
                              void* d_out, int out_size) {
    const float* x   = (const float*)d_in[0];
    const int*   ei  = (const int*)d_in[1];
    const float* Wl1 = (const float*)d_in[2];
    const float* Wr1 = (const float*)d_in[3];
    const float* b1  = (const float*)d_in[4];
    const float* Wl2 = (const float*)d_in[5];
    const float* Wr2 = (const float*)d_in[6];
    const float* b2  = (const float*)d_in[7];
    float* out = (float*)d_out;

    const int* src = ei;
    const int* dst = ei + N_EDGES;

    __half *xh, *hh, *aggh, *wt;
    int* cnt;
    cudaGetSymbolAddress((void**)&xh, g_xh);
    cudaGetSymbolAddress((void**)&hh, g_hh);
    cudaGetSymbolAddress((void**)&aggh, g_aggh);
    cudaGetSymbolAddress((void**)&wt, g_wt);
    cudaGetSymbolAddress((void**)&cnt, g_count);

    __half* wl1h = wt;           // [128][128]
    __half* wr1h = wt + 16384;   // [128][128]
    __half* wl2h = wt + 32768;   // [64][128]
    __half* wr2h = wt + 40960;   // [64][128]

    // smem: 2 W matrices (WST=136) + 2 A stages (AST=72) + bias + ssq
    const int SMEM1 = 2 * (128 * 136 * 2) + 2 * (128 * 72 * 2) + (128 + 128) * 4;  // 107520
    const int SMEM2 = 2 * (64 * 136 * 2)  + 2 * (128 * 72 * 2) + (64 + 128) * 4;   // 72448
    cudaFuncSetAttribute(k_gemm_mma<128, true, true>,
                         cudaFuncAttributeMaxDynamicSharedMemorySize, SMEM1);
    cudaFuncSetAttribute(k_gemm_mma<64, false, false>,
                         cudaFuncAttributeMaxDynamicSharedMemorySize, SMEM2);

    // fused prep: xconv | wprep | hist (cnt zeroed first; also resets scan flag)
    cudaMemsetAsync(cnt, 0, N_NODES * sizeof(int));
    k_prep<<<XSPLIT_BLOCKS + WPREP_BLOCKS + HIST_BLOCKS, 256>>>(
        x, xh, Wl1, Wr1, Wl2, Wr2, wt, dst);

    // CSR build: fused scan + bin (max-aggregation is order-invariant -> deterministic)
    k_scan_bin<<<SCAN_BLOCKS, 1024>>>(src, dst);

    const int segmax_blocks = (N_NODES * 16 + 255) / 256;   // 6250
    const int gemm_blocks   = (N_NODES + 127) / 128;        // 782

    // layer 1: C = aggh@Wl1h + xh@Wr1h
    k_segmax_h<<<segmax_blocks, 256>>>(xh, aggh);
    k_gemm_mma<128, true, true><<<gemm_blocks, 256, SMEM1>>>(
        aggh, xh, wl1h, wr1h, b1, nullptr, hh);

    // layer 2: C = aggh@Wl2h + hh@Wr2h
    k_segmax_h<<<segmax_blocks, 256>>>(hh, aggh);
    k_gemm_mma<64, false, false><<<gemm_blocks, 256, SMEM2>>>(
        aggh, hh, wl2h, wr2h, b2, out, nullptr);
}